// round 11
// baseline (speedup 1.0000x reference)
#include <cuda_runtime.h>
#include <cuda_bf16.h>
#include <math.h>
#include <stdint.h>

#define E    11
#define KSEL 6
#define P    64
#define NH   4
#define HD   16
#define SEQ  12
#define BB   8
#define C    128
#define HH   64
#define WW   64
#define HW   (HH*WW)        /* 4096  */
#define NPIX (BB*HW)        /* 32768 */
#define HID  512
#define LDT  136            /* smem tile row stride in bf16 (272B = 17*16B, conflict-free) */

// ---------------- device scratch (no allocation allowed) ----------------
__device__ float g_gc[BB*C];
__device__ float g_Wr[BB*E*C];
__device__ float g_br[BB*E];
__device__ float g_route[E*NPIX];
__device__ float g_probsum[E];
__device__ float g_loadsum[E];
__device__ int   g_cnt[E];
__device__ int   g_pidx[E*NPIX];   // [e][slot] -> pixel
__device__ int   g_slot[E*NPIX];   // [e][pixel] -> slot
__device__ float g_ybuf[E*NPIX*C]; // [e][slot][c]
__device__ __align__(16) __nv_bfloat16 g_w1h[E*HID*C];  // [e][r][c]
__device__ __align__(16) __nv_bfloat16 g_w2h[E*C*HID];  // [e][c][j]

// ---------------- mma/ldmatrix helpers (sm_80-era, no 'a' gating) --------
__device__ __forceinline__ uint32_t smem_u32(const void* p) {
    uint32_t a;
    asm("{ .reg .u64 t; cvta.to.shared.u64 t, %1; cvt.u32.u64 %0, t; }"
        : "=r"(a) : "l"(p));
    return a;
}
__device__ __forceinline__ void ldsm4(uint32_t a, uint32_t* r) {
    asm volatile("ldmatrix.sync.aligned.m8n8.x4.shared.b16 {%0,%1,%2,%3}, [%4];"
        : "=r"(r[0]), "=r"(r[1]), "=r"(r[2]), "=r"(r[3]) : "r"(a));
}
__device__ __forceinline__ void mma16816(float* c, const uint32_t* a, const uint32_t* b) {
    asm volatile("mma.sync.aligned.m16n8k16.row.col.f32.bf16.bf16.f32 "
        "{%0,%1,%2,%3}, {%4,%5,%6,%7}, {%8,%9}, {%0,%1,%2,%3};"
        : "+f"(c[0]), "+f"(c[1]), "+f"(c[2]), "+f"(c[3])
        : "r"(a[0]), "r"(a[1]), "r"(a[2]), "r"(a[3]), "r"(b[0]), "r"(b[1]));
}
__device__ __forceinline__ uint32_t pack_bf2(float x, float y) {
    __nv_bfloat162 v = __floats2bfloat162_rn(x, y);
    return *reinterpret_cast<uint32_t*>(&v);
}

// ---------------- prep: convert weights to bf16 ---------------------------
__global__ void k_cvt(const float* __restrict__ ew1, const float* __restrict__ ew2) {
    int i = blockIdx.x * 256 + threadIdx.x;
    if (i < E*HID*C) {
        g_w1h[i] = __float2bfloat16(ew1[i]);
        g_w2h[i] = __float2bfloat16(ew2[i]);
    }
}

// ---------------- kernel 0: global-context means + zero counters --------
__global__ void k_gc(const float* __restrict__ x) {
    int bc = blockIdx.x;
    const float4* src = reinterpret_cast<const float4*>(x + (size_t)bc * HW);
    float s = 0.f;
    for (int i = threadIdx.x; i < HW/4; i += 128) {
        float4 v = src[i];
        s += v.x + v.y + v.z + v.w;
    }
    __shared__ float red[4];
    for (int o = 16; o; o >>= 1) s += __shfl_down_sync(0xffffffffu, s, o);
    if ((threadIdx.x & 31) == 0) red[threadIdx.x >> 5] = s;
    __syncthreads();
    if (threadIdx.x == 0) {
        float t = red[0] + red[1] + red[2] + red[3];
        g_gc[bc] = t * (1.0f / HW);
    }
    if (bc == 0 && threadIdx.x < E) {
        g_probsum[threadIdx.x] = 0.f;
        g_loadsum[threadIdx.x] = 0.f;
        g_cnt[threadIdx.x] = 0;
    }
}

// ---------------- kernel A: attention path + router weight folding ------
// Weights staged into dynamic smem (coalesced float4 once), phases read smem.
__global__ void k_attn(const float* __restrict__ proto,
                       const float* __restrict__ ctx_w, const float* __restrict__ ctx_b,
                       const float* __restrict__ inp_w, const float* __restrict__ inp_b,
                       const float* __restrict__ wq, const float* __restrict__ bq,
                       const float* __restrict__ wk, const float* __restrict__ bk,
                       const float* __restrict__ wv, const float* __restrict__ bv,
                       const float* __restrict__ wo, const float* __restrict__ bo,
                       const float* __restrict__ ln_g, const float* __restrict__ ln_b) {
    extern __shared__ float wsm[];
    float* swq  = wsm;               // P*P = 4096
    float* swk  = swq + P*P;
    float* swv  = swk + P*P;
    float* swo  = swv + P*P;
    float* sctx = swo + P*P;         // P*C = 8192
    float* sinp = sctx + P*C;        // P*C = 8192

    int b = blockIdx.x;
    int t = threadIdx.x;                       // 256 threads
    __shared__ float seq[SEQ][P], qs[SEQ][P], ks[SEQ][P], vs[SEQ][P], ao[SEQ][P], o2[SEQ][P];
    __shared__ float gx[C];
    __shared__ float mstat[SEQ], istat[SEQ];

    {
        const float4* s4;
        float4* d4;
        s4 = reinterpret_cast<const float4*>(wq);  d4 = reinterpret_cast<float4*>(swq);
        for (int i = t; i < P*P/4; i += 256) d4[i] = s4[i];
        s4 = reinterpret_cast<const float4*>(wk);  d4 = reinterpret_cast<float4*>(swk);
        for (int i = t; i < P*P/4; i += 256) d4[i] = s4[i];
        s4 = reinterpret_cast<const float4*>(wv);  d4 = reinterpret_cast<float4*>(swv);
        for (int i = t; i < P*P/4; i += 256) d4[i] = s4[i];
        s4 = reinterpret_cast<const float4*>(wo);  d4 = reinterpret_cast<float4*>(swo);
        for (int i = t; i < P*P/4; i += 256) d4[i] = s4[i];
        s4 = reinterpret_cast<const float4*>(ctx_w); d4 = reinterpret_cast<float4*>(sctx);
        for (int i = t; i < P*C/4; i += 256) d4[i] = s4[i];
        s4 = reinterpret_cast<const float4*>(inp_w); d4 = reinterpret_cast<float4*>(sinp);
        for (int i = t; i < P*C/4; i += 256) d4[i] = s4[i];
    }
    if (t < C) gx[t] = g_gc[b*C + t];
    __syncthreads();

    if (t < P) {
        float a = ctx_b[t];
        for (int c = 0; c < C; c++) a += gx[c] * sctx[t*C + c];
        seq[0][t] = a;
    }
    for (int z = t; z < E*P; z += 256) seq[1 + z/P][z%P] = proto[z];
    __syncthreads();

    for (int z = t; z < SEQ*P; z += 256) {
        int s = z >> 6, p = z & 63;
        float aq = bq[p], ak = bk[p], av = bv[p];
        for (int q = 0; q < P; q++) {
            float sv = seq[s][q];
            aq += sv * swq[p*P + q];
            ak += sv * swk[p*P + q];
            av += sv * swv[p*P + q];
        }
        qs[s][p] = aq; ks[s][p] = ak; vs[s][p] = av;
    }
    __syncthreads();

    if (t < NH*SEQ) {
        int n = t / SEQ, i = t % SEQ;
        float sc[SEQ];
        float mx = -1e30f;
        for (int j = 0; j < SEQ; j++) {
            float a = 0.f;
            for (int d = 0; d < HD; d++) a += qs[i][n*HD + d] * ks[j][n*HD + d];
            a *= 0.25f;
            sc[j] = a; mx = fmaxf(mx, a);
        }
        float sm = 0.f;
        for (int j = 0; j < SEQ; j++) { sc[j] = expf(sc[j] - mx); sm += sc[j]; }
        float inv = 1.0f / sm;
        for (int d = 0; d < HD; d++) {
            float a = 0.f;
            for (int j = 0; j < SEQ; j++) a += sc[j] * vs[j][n*HD + d];
            ao[i][n*HD + d] = a * inv;
        }
    }
    __syncthreads();

    for (int z = t; z < SEQ*P; z += 256) {
        int s = z >> 6, p = z & 63;
        float a = bo[p];
        for (int q = 0; q < P; q++) a += ao[s][q] * swo[p*P + q];
        o2[s][p] = a + seq[s][p];
    }
    __syncthreads();

    if (t < SEQ) {
        float m = 0.f;
        for (int p = 0; p < P; p++) m += o2[t][p];
        m *= (1.0f / P);
        float v = 0.f;
        for (int p = 0; p < P; p++) { float d = o2[t][p] - m; v += d*d; }
        v *= (1.0f / P);
        mstat[t] = m; istat[t] = 1.0f / sqrtf(v + 1e-5f);
    }
    __syncthreads();

    for (int z = t; z < E*P; z += 256) {
        int s = z / P + 1, p = z % P;
        seq[s][p] = (o2[s][p] - mstat[s]) * istat[s] * ln_g[p] + ln_b[p];
    }
    __syncthreads();

    for (int z = t; z < E*C; z += 256) {
        int e = z / C, c = z % C;
        float a = 0.f;
        for (int p = 0; p < P; p++) a += seq[e+1][p] * sinp[p*C + c];
        g_Wr[(b*E + e)*C + c] = a;
    }
    if (t < E) {
        float a = 0.f;
        for (int p = 0; p < P; p++) a += seq[t+1][p] * inp_b[p];
        g_br[b*E + t] = a;
    }
}

// ---------------- kernel B: routing + per-expert compaction -------------
// 128 threads/block, 2 pixels/thread via float2 loads, c-loop unrolled 8x.
__global__ void k_route(const float* __restrict__ x) {
    const int t = threadIdx.x;                 // 128
    const int base = blockIdx.x * 256;         // 256 pixels per block
    const int b = base / HW;                   // whole block same batch (256 | 4096)
    const int pix0 = base + t * 2;

    __shared__ float wr[E*C];
    __shared__ float br[E];
    __shared__ float psum[E];
    __shared__ int   scnt[E], sbase[E];
    for (int i = t; i < E*C; i += 128) wr[i] = g_Wr[b*E*C + i];
    if (t < E) {
        br[t] = g_br[b*E + t];
        psum[t] = 0.f;
        scnt[t] = 0;
    }
    __syncthreads();

    float pr[2][E];
    #pragma unroll
    for (int e = 0; e < E; e++) { pr[0][e] = br[e]; pr[1][e] = br[e]; }

    const float* xp = x + (size_t)b*C*HW + (pix0 - b*HW);
    #pragma unroll 8
    for (int c = 0; c < C; c++) {
        float2 xv = *reinterpret_cast<const float2*>(xp + (size_t)c * HW);
        #pragma unroll
        for (int e = 0; e < E; e++) {
            float w = wr[e*C + c];
            pr[0][e] += xv.x * w;
            pr[1][e] += xv.y * w;
        }
    }

    #pragma unroll
    for (int px = 0; px < 2; px++) {
        int pix = pix0 + px;
        float mx = -1e30f;
        #pragma unroll
        for (int e = 0; e < E; e++) { pr[px][e] *= 0.125f; mx = fmaxf(mx, pr[px][e]); }
        float sm = 0.f;
        #pragma unroll
        for (int e = 0; e < E; e++) { pr[px][e] = expf(pr[px][e] - mx); sm += pr[px][e]; }
        float invs = 1.0f / sm;
        #pragma unroll
        for (int e = 0; e < E; e++) pr[px][e] *= invs;

        int used = 0;
        float tsum = 0.f;
        #pragma unroll
        for (int k2 = 0; k2 < KSEL; k2++) {
            float bv = -1.f; int bi = 0;
            #pragma unroll
            for (int e = 0; e < E; e++)
                if (!((used >> e) & 1) && pr[px][e] > bv) { bv = pr[px][e]; bi = e; }
            used |= 1 << bi;
            tsum += bv;
        }
        float invt = 1.0f / tsum;

        #pragma unroll
        for (int e = 0; e < E; e++) {
            int selq = (used >> e) & 1;
            g_route[(size_t)e * NPIX + pix] = selq ? pr[px][e] * invt : 0.f;
            atomicAdd(&psum[e], pr[px][e]);
            if (selq) {
                int loc = atomicAdd(&scnt[e], 1);
                // stash local slot in pr to use after block-level base known
                pr[px][e] = __int_as_float(loc);
            } else {
                pr[px][e] = __int_as_float(-1);
            }
        }
    }
    __syncthreads();
    if (t < E) {
        sbase[t] = atomicAdd(&g_cnt[t], scnt[t]);
        atomicAdd(&g_probsum[t], psum[t]);
        atomicAdd(&g_loadsum[t], (float)scnt[t]);
    }
    __syncthreads();
    #pragma unroll
    for (int px = 0; px < 2; px++) {
        int pix = pix0 + px;
        #pragma unroll
        for (int e = 0; e < E; e++) {
            int loc = __float_as_int(pr[px][e]);
            if (loc >= 0) {
                int slot = sbase[e] + loc;
                g_pidx[e*NPIX + slot] = pix;
                g_slot[e*NPIX + pix]  = slot;
            }
        }
    }
}

// ---------------- kernel C: HMMA grouped-GEMM expert MLPs ----------------
__global__ void __launch_bounds__(256, 1)
k_mlp(const float* __restrict__ x,
      const float* __restrict__ eb1,
      const float* __restrict__ eb2) {
    extern __shared__ __align__(16) __nv_bfloat16 sm[];
    __nv_bfloat16* Xh = sm;                  // [128][LDT]
    __nv_bfloat16* Wh = Xh + 128*LDT;
    __nv_bfloat16* Hh = Wh + 128*LDT;
    __shared__ int   pid[128];
    __shared__ float bias1[128], bias2[128];

    const int e     = blockIdx.y;
    const int cnt   = g_cnt[e];
    const int tile0 = blockIdx.x * 128;
    if (tile0 >= cnt) return;
    const int rem = min(128, cnt - tile0);
    const int tid = threadIdx.x;
    const int wid = tid >> 5, lane = tid & 31;

    if (tid < 128) {
        pid[tid]   = g_pidx[e*NPIX + tile0 + min(tid, rem - 1)];
        bias2[tid] = eb2[(size_t)e*C + tid];
    }
    __syncthreads();

    // gather X -> bf16 [slot][c]
    for (int idx = tid; idx < 128*128; idx += 256) {
        int slot = idx & 127, c = idx >> 7;
        int p = pid[slot];
        int b = p >> 12;
        float v = x[(size_t)b*(C-1)*HW + (size_t)c*HW + p];
        Xh[slot*LDT + c] = __float2bfloat16(v);
    }

    const __nv_bfloat16* w1h = g_w1h + (size_t)e*HID*C;
    const __nv_bfloat16* w2h = g_w2h + (size_t)e*C*HID;

    const int m0 = (wid >> 1) * 32;
    const int n0 = (wid & 1) * 64;
    const int lr = lane & 7, lq = lane >> 3;
    const int aoff = ((lr + (lq & 1)*8) * LDT + (lq >> 1)*8) * 2;
    const int boff = ((lr + (lq >> 1)*8) * LDT + (lq & 1)*8) * 2;
    const int er = lane >> 2;
    const int ec = (lane & 3) * 2;

    const uint32_t uXh = smem_u32(Xh);
    const uint32_t uWh = smem_u32(Wh);
    const uint32_t uHh = smem_u32(Hh);

    const uint32_t aXh = uXh + m0*LDT*2 + aoff;
    const uint32_t aHh = uHh + m0*LDT*2 + aoff;
    const uint32_t bWh = uWh + n0*LDT*2 + boff;

    float yacc[2][8][4];
    #pragma unroll
    for (int mt = 0; mt < 2; mt++)
        #pragma unroll
        for (int nt = 0; nt < 8; nt++)
            #pragma unroll
            for (int q = 0; q < 4; q++) yacc[mt][nt][q] = 0.f;

    for (int rc = 0; rc < 4; rc++) {
        const int r0 = rc * 128;
        __syncthreads();

        for (int idx = tid; idx < 128*16; idx += 256) {
            int row = idx >> 4, q = idx & 15;
            *reinterpret_cast<uint4*>(Wh + row*LDT + q*8) =
                *reinterpret_cast<const uint4*>(w1h + (size_t)(r0+row)*C + q*8);
        }
        if (tid < 128) bias1[tid] = eb1[(size_t)e*HID + r0 + tid];
        __syncthreads();

        // ---- GEMM1
        float h[2][8][4];
        #pragma unroll
        for (int mt = 0; mt < 2; mt++)
            #pragma unroll
            for (int nt = 0; nt < 8; nt++)
                #pragma unroll
                for (int q = 0; q < 4; q++) h[mt][nt][q] = 0.f;

        #pragma unroll 2
        for (int ks2 = 0; ks2 < 8; ks2++) {
            const uint32_t kb = ks2 * 32;
            uint32_t ah[2][4];
            ldsm4(aXh + kb,             ah[0]);
            ldsm4(aXh + kb + 16*LDT*2,  ah[1]);
            #pragma unroll
            for (int ntp = 0; ntp < 4; ntp++) {
                uint32_t bh[4];
                ldsm4(bWh + ntp*16*LDT*2 + kb, bh);
                #pragma unroll
                for (int mt = 0; mt < 2; mt++) {
                    mma16816(h[mt][ntp*2],   ah[mt], bh);
                    mma16816(h[mt][ntp*2+1], ah[mt], bh + 2);
                }
            }
        }

        // ---- gelu + bias -> Hh
        #pragma unroll
        for (int mt = 0; mt < 2; mt++) {
            #pragma unroll
            for (int nt = 0; nt < 8; nt++) {
                int gm = m0 + mt*16 + er;
                int gn = n0 + nt*8 + ec;
                float b1a = bias1[gn], b1b = bias1[gn+1];
                float u0 = h[mt][nt][0] + b1a;
                float u1 = h[mt][nt][1] + b1b;
                float u2 = h[mt][nt][2] + b1a;
                float u3 = h[mt][nt][3] + b1b;
                u0 = 0.5f*u0*(1.0f + erff(u0*0.70710678118654752f));
                u1 = 0.5f*u1*(1.0f + erff(u1*0.70710678118654752f));
                u2 = 0.5f*u2*(1.0f + erff(u2*0.70710678118654752f));
                u3 = 0.5f*u3*(1.0f + erff(u3*0.70710678118654752f));
                *reinterpret_cast<uint32_t*>(Hh + gm*LDT + gn)     = pack_bf2(u0, u1);
                *reinterpret_cast<uint32_t*>(Hh + (gm+8)*LDT + gn) = pack_bf2(u2, u3);
            }
        }
        __syncthreads();

        for (int idx = tid; idx < 128*16; idx += 256) {
            int row = idx >> 4, q = idx & 15;
            *reinterpret_cast<uint4*>(Wh + row*LDT + q*8) =
                *reinterpret_cast<const uint4*>(w2h + (size_t)row*HID + r0 + q*8);
        }
        __syncthreads();

        // ---- GEMM2
        #pragma unroll 2
        for (int ks2 = 0; ks2 < 8; ks2++) {
            const uint32_t kb = ks2 * 32;
            uint32_t ah[2][4];
            ldsm4(aHh + kb,            ah[0]);
            ldsm4(aHh + kb + 16*LDT*2, ah[1]);
            #pragma unroll
            for (int ntp = 0; ntp < 4; ntp++) {
                uint32_t bh[4];
                ldsm4(bWh + ntp*16*LDT*2 + kb, bh);
                #pragma unroll
                for (int mt = 0; mt < 2; mt++) {
                    mma16816(yacc[mt][ntp*2],   ah[mt], bh);
                    mma16816(yacc[mt][ntp*2+1], ah[mt], bh + 2);
                }
            }
        }
    }

    // ---- epilogue
    #pragma unroll
    for (int mt = 0; mt < 2; mt++) {
        #pragma unroll
        for (int nt = 0; nt < 8; nt++) {
            int slot = m0 + mt*16 + er;
            int cc   = n0 + nt*8 + ec;
            float b2a = bias2[cc], b2b = bias2[cc+1];
            if (slot < rem) {
                float2 o = { yacc[mt][nt][0] + b2a, yacc[mt][nt][1] + b2b };
                *reinterpret_cast<float2*>(
                    g_ybuf + ((size_t)e*NPIX + tile0 + slot)*C + cc) = o;
            }
            if (slot + 8 < rem) {
                float2 o = { yacc[mt][nt][2] + b2a, yacc[mt][nt][3] + b2b };
                *reinterpret_cast<float2*>(
                    g_ybuf + ((size_t)e*NPIX + tile0 + slot + 8)*C + cc) = o;
            }
        }
    }
}

// ---------------- kernel G: weighted gather + residual ------------------
__global__ void k_gather(const float* __restrict__ x, float* __restrict__ out) {
    __shared__ float tile[C*33];
    const int t = threadIdx.x;
    const int lane = t & 31, w = t >> 5;
    const int pix0 = blockIdx.x * 32;
    const int b = pix0 >> 12;

    #pragma unroll
    for (int k = 0; k < 4; k++) {
        int px  = w*4 + k;
        int pix = pix0 + px;
        float a0 = 0.f, a1 = 0.f, a2 = 0.f, a3 = 0.f;
        #pragma unroll
        for (int e = 0; e < E; e++) {
            float wv = g_route[(size_t)e*NPIX + pix];
            if (wv > 0.f) {
                int sl = g_slot[e*NPIX + pix];
                const float* row = g_ybuf + ((size_t)e*NPIX + sl)*C;
                a0 += wv * row[lane];
                a1 += wv * row[lane + 32];
                a2 += wv * row[lane + 64];
                a3 += wv * row[lane + 96];
            }
        }
        tile[(lane)*33 + px]      = a0;
        tile[(lane+32)*33 + px]   = a1;
        tile[(lane+64)*33 + px]   = a2;
        tile[(lane+96)*33 + px]   = a3;
    }
    __syncthreads();
    const size_t base = (size_t)b*(C-1)*HW + pix0;
    for (int idx = t; idx < C*32; idx += 256) {
        int c = idx >> 5, px = idx & 31;
        size_t a = base + (size_t)c*HW + px;
        out[a] = x[a] + tile[c*33 + px];
    }
}

// ---------------- kernel D: aux scalar -----------------------------------
__global__ void k_aux(const float* __restrict__ proto, float* __restrict__ out, int out_size) {
    __shared__ float pn[E][P];
    __shared__ float red[128];
    int t = threadIdx.x;
    if (t < E) {
        float s = 0.f;
        for (int p = 0; p < P; p++) { float v = proto[t*P + p]; s += v*v; }
        float inv = 1.0f / sqrtf(s);
        for (int p = 0; p < P; p++) pn[t][p] = proto[t*P + p] * inv;
    }
    __syncthreads();
    float s = 0.f;
    for (int idx = t; idx < E*E; idx += 128) {
        int i = idx / E, j = idx % E;
        float d = 0.f;
        for (int p = 0; p < P; p++) d += pn[i][p] * pn[j][p];
        d -= (i == j) ? 1.0f : 0.0f;
        s += d*d;
    }
    red[t] = s;
    __syncthreads();
    for (int st = 64; st; st >>= 1) { if (t < st) red[t] += red[t + st]; __syncthreads(); }
    if (t == 0) {
        float ortho = sqrtf(red[0]);
        float aux = 0.f;
        for (int e = 0; e < E; e++)
            aux += (g_probsum[e] * (1.0f/NPIX)) * (g_loadsum[e] * (1.0f/NPIX));
        aux *= (float)E;
        if (out_size > BB*C*HW) out[BB*C*HW] = aux + 0.5f * ortho;
    }
}

// ---------------- launcher ------------------------------------------------
extern "C" void kernel_launch(void* const* d_in, const int* in_sizes, int n_in,
                              void* d_out, int out_size) {
    const float* x      = (const float*)d_in[0];
    const float* proto  = (const float*)d_in[1];
    const float* ctx_w  = (const float*)d_in[2];
    const float* ctx_b  = (const float*)d_in[3];
    const float* inp_w  = (const float*)d_in[4];
    const float* inp_b  = (const float*)d_in[5];
    const float* wq     = (const float*)d_in[6];
    const float* bq     = (const float*)d_in[7];
    const float* wk     = (const float*)d_in[8];
    const float* bk     = (const float*)d_in[9];
    const float* wv     = (const float*)d_in[10];
    const float* bv     = (const float*)d_in[11];
    const float* wo     = (const float*)d_in[12];
    const float* bo     = (const float*)d_in[13];
    const float* ln_g   = (const float*)d_in[14];
    const float* ln_b   = (const float*)d_in[15];
    const float* ew1    = (const float*)d_in[16];
    const float* eb1    = (const float*)d_in[17];
    const float* ew2    = (const float*)d_in[18];
    const float* eb2    = (const float*)d_in[19];
    float* out = (float*)d_out;

    const int smem_mlp  = 3 * 128 * LDT * (int)sizeof(__nv_bfloat16);  // 104448 B
    const int smem_attn = (4*P*P + 2*P*C) * (int)sizeof(float);        // 131072 B
    cudaFuncSetAttribute(k_mlp,  cudaFuncAttributeMaxDynamicSharedMemorySize, smem_mlp);
    cudaFuncSetAttribute(k_attn, cudaFuncAttributeMaxDynamicSharedMemorySize, smem_attn);

    k_cvt<<<(E*HID*C + 255)/256, 256>>>(ew1, ew2);
    k_gc<<<BB*C, 128>>>(x);
    k_attn<<<BB, 256, smem_attn>>>(proto, ctx_w, ctx_b, inp_w, inp_b,
                                   wq, bq, wk, bk, wv, bv, wo, bo, ln_g, ln_b);
    k_route<<<NPIX/256, 128>>>(x);
    k_mlp<<<dim3(NPIX/128, E), 256, smem_mlp>>>(x, eb1, eb2);
    k_gather<<<NPIX/32, 256>>>(x, out);
    k_aux<<<1, 128>>>(proto, out, out_size);
}

// round 12
// speedup vs baseline: 1.0880x; 1.0880x over previous
#include <cuda_runtime.h>
#include <cuda_bf16.h>
#include <math.h>
#include <stdint.h>

#define E    11
#define KSEL 6
#define P    64
#define NH   4
#define HD   16
#define SEQ  12
#define BB   8
#define C    128
#define HH   64
#define WW   64
#define HW   (HH*WW)        /* 4096  */
#define NPIX (BB*HW)        /* 32768 */
#define HID  512
#define LDT  136            /* smem tile row stride in bf16 (272B = 17*16B, conflict-free) */

// ---------------- device scratch (no allocation allowed) ----------------
__device__ float g_gc[BB*C];
__device__ float g_Wr[BB*E*C];
__device__ float g_br[BB*E];
__device__ float g_route[E*NPIX];
__device__ float g_probsum[E];
__device__ float g_loadsum[E];
__device__ int   g_cnt[E];
__device__ int   g_pidx[E*NPIX];   // [e][slot] -> pixel
__device__ int   g_slot[E*NPIX];   // [e][pixel] -> slot
__device__ float g_ybuf[E*NPIX*C]; // [e][slot][c]
__device__ __align__(16) __nv_bfloat16 g_w1h[E*HID*C];  // [e][r][c]
__device__ __align__(16) __nv_bfloat16 g_w2h[E*C*HID];  // [e][c][j]

// ---------------- mma/ldmatrix helpers (sm_80-era, no 'a' gating) --------
__device__ __forceinline__ uint32_t smem_u32(const void* p) {
    uint32_t a;
    asm("{ .reg .u64 t; cvta.to.shared.u64 t, %1; cvt.u32.u64 %0, t; }"
        : "=r"(a) : "l"(p));
    return a;
}
__device__ __forceinline__ void ldsm4(uint32_t a, uint32_t* r) {
    asm volatile("ldmatrix.sync.aligned.m8n8.x4.shared.b16 {%0,%1,%2,%3}, [%4];"
        : "=r"(r[0]), "=r"(r[1]), "=r"(r[2]), "=r"(r[3]) : "r"(a));
}
__device__ __forceinline__ void mma16816(float* c, const uint32_t* a, const uint32_t* b) {
    asm volatile("mma.sync.aligned.m16n8k16.row.col.f32.bf16.bf16.f32 "
        "{%0,%1,%2,%3}, {%4,%5,%6,%7}, {%8,%9}, {%0,%1,%2,%3};"
        : "+f"(c[0]), "+f"(c[1]), "+f"(c[2]), "+f"(c[3])
        : "r"(a[0]), "r"(a[1]), "r"(a[2]), "r"(a[3]), "r"(b[0]), "r"(b[1]));
}
__device__ __forceinline__ uint32_t pack_bf2(float x, float y) {
    __nv_bfloat162 v = __floats2bfloat162_rn(x, y);
    return *reinterpret_cast<uint32_t*>(&v);
}

// ---------------- prep: convert weights to bf16 ---------------------------
__global__ void k_cvt(const float* __restrict__ ew1, const float* __restrict__ ew2) {
    int i = blockIdx.x * 256 + threadIdx.x;
    if (i < E*HID*C) {
        g_w1h[i] = __float2bfloat16(ew1[i]);
        g_w2h[i] = __float2bfloat16(ew2[i]);
    }
}

// ---------------- kernel 0: global-context means + zero counters --------
__global__ void k_gc(const float* __restrict__ x) {
    int bc = blockIdx.x;
    const float4* src = reinterpret_cast<const float4*>(x + (size_t)bc * HW);
    float s = 0.f;
    for (int i = threadIdx.x; i < HW/4; i += 128) {
        float4 v = src[i];
        s += v.x + v.y + v.z + v.w;
    }
    __shared__ float red[4];
    for (int o = 16; o; o >>= 1) s += __shfl_down_sync(0xffffffffu, s, o);
    if ((threadIdx.x & 31) == 0) red[threadIdx.x >> 5] = s;
    __syncthreads();
    if (threadIdx.x == 0) {
        float t = red[0] + red[1] + red[2] + red[3];
        g_gc[bc] = t * (1.0f / HW);
    }
    if (bc == 0 && threadIdx.x < E) {
        g_probsum[threadIdx.x] = 0.f;
        g_loadsum[threadIdx.x] = 0.f;
        g_cnt[threadIdx.x] = 0;
    }
}

// ---------------- kernel A: attention path + router weight folding ------
// Weights staged into dynamic smem (coalesced float4 once), phases read smem.
__global__ void k_attn(const float* __restrict__ proto,
                       const float* __restrict__ ctx_w, const float* __restrict__ ctx_b,
                       const float* __restrict__ inp_w, const float* __restrict__ inp_b,
                       const float* __restrict__ wq, const float* __restrict__ bq,
                       const float* __restrict__ wk, const float* __restrict__ bk,
                       const float* __restrict__ wv, const float* __restrict__ bv,
                       const float* __restrict__ wo, const float* __restrict__ bo,
                       const float* __restrict__ ln_g, const float* __restrict__ ln_b) {
    extern __shared__ float wsm[];
    float* swq  = wsm;               // P*P = 4096
    float* swk  = swq + P*P;
    float* swv  = swk + P*P;
    float* swo  = swv + P*P;
    float* sctx = swo + P*P;         // P*C = 8192
    float* sinp = sctx + P*C;        // P*C = 8192

    int b = blockIdx.x;
    int t = threadIdx.x;                       // 256 threads
    __shared__ float seq[SEQ][P], qs[SEQ][P], ks[SEQ][P], vs[SEQ][P], ao[SEQ][P], o2[SEQ][P];
    __shared__ float gx[C];
    __shared__ float mstat[SEQ], istat[SEQ];

    {
        const float4* s4;
        float4* d4;
        s4 = reinterpret_cast<const float4*>(wq);  d4 = reinterpret_cast<float4*>(swq);
        for (int i = t; i < P*P/4; i += 256) d4[i] = s4[i];
        s4 = reinterpret_cast<const float4*>(wk);  d4 = reinterpret_cast<float4*>(swk);
        for (int i = t; i < P*P/4; i += 256) d4[i] = s4[i];
        s4 = reinterpret_cast<const float4*>(wv);  d4 = reinterpret_cast<float4*>(swv);
        for (int i = t; i < P*P/4; i += 256) d4[i] = s4[i];
        s4 = reinterpret_cast<const float4*>(wo);  d4 = reinterpret_cast<float4*>(swo);
        for (int i = t; i < P*P/4; i += 256) d4[i] = s4[i];
        s4 = reinterpret_cast<const float4*>(ctx_w); d4 = reinterpret_cast<float4*>(sctx);
        for (int i = t; i < P*C/4; i += 256) d4[i] = s4[i];
        s4 = reinterpret_cast<const float4*>(inp_w); d4 = reinterpret_cast<float4*>(sinp);
        for (int i = t; i < P*C/4; i += 256) d4[i] = s4[i];
    }
    if (t < C) gx[t] = g_gc[b*C + t];
    __syncthreads();

    if (t < P) {
        float a = ctx_b[t];
        for (int c = 0; c < C; c++) a += gx[c] * sctx[t*C + c];
        seq[0][t] = a;
    }
    for (int z = t; z < E*P; z += 256) seq[1 + z/P][z%P] = proto[z];
    __syncthreads();

    for (int z = t; z < SEQ*P; z += 256) {
        int s = z >> 6, p = z & 63;
        float aq = bq[p], ak = bk[p], av = bv[p];
        for (int q = 0; q < P; q++) {
            float sv = seq[s][q];
            aq += sv * swq[p*P + q];
            ak += sv * swk[p*P + q];
            av += sv * swv[p*P + q];
        }
        qs[s][p] = aq; ks[s][p] = ak; vs[s][p] = av;
    }
    __syncthreads();

    if (t < NH*SEQ) {
        int n = t / SEQ, i = t % SEQ;
        float sc[SEQ];
        float mx = -1e30f;
        for (int j = 0; j < SEQ; j++) {
            float a = 0.f;
            for (int d = 0; d < HD; d++) a += qs[i][n*HD + d] * ks[j][n*HD + d];
            a *= 0.25f;
            sc[j] = a; mx = fmaxf(mx, a);
        }
        float sm = 0.f;
        for (int j = 0; j < SEQ; j++) { sc[j] = expf(sc[j] - mx); sm += sc[j]; }
        float inv = 1.0f / sm;
        for (int d = 0; d < HD; d++) {
            float a = 0.f;
            for (int j = 0; j < SEQ; j++) a += sc[j] * vs[j][n*HD + d];
            ao[i][n*HD + d] = a * inv;
        }
    }
    __syncthreads();

    for (int z = t; z < SEQ*P; z += 256) {
        int s = z >> 6, p = z & 63;
        float a = bo[p];
        for (int q = 0; q < P; q++) a += ao[s][q] * swo[p*P + q];
        o2[s][p] = a + seq[s][p];
    }
    __syncthreads();

    if (t < SEQ) {
        float m = 0.f;
        for (int p = 0; p < P; p++) m += o2[t][p];
        m *= (1.0f / P);
        float v = 0.f;
        for (int p = 0; p < P; p++) { float d = o2[t][p] - m; v += d*d; }
        v *= (1.0f / P);
        mstat[t] = m; istat[t] = 1.0f / sqrtf(v + 1e-5f);
    }
    __syncthreads();

    for (int z = t; z < E*P; z += 256) {
        int s = z / P + 1, p = z % P;
        seq[s][p] = (o2[s][p] - mstat[s]) * istat[s] * ln_g[p] + ln_b[p];
    }
    __syncthreads();

    for (int z = t; z < E*C; z += 256) {
        int e = z / C, c = z % C;
        float a = 0.f;
        for (int p = 0; p < P; p++) a += seq[e+1][p] * sinp[p*C + c];
        g_Wr[(b*E + e)*C + c] = a;
    }
    if (t < E) {
        float a = 0.f;
        for (int p = 0; p < P; p++) a += seq[t+1][p] * inp_b[p];
        g_br[b*E + t] = a;
    }
}

// ---------------- kernel B: routing + per-expert compaction -------------
// 256 threads, 1 px/thread (R8 shape) + manual 4x c-unroll for load MLP.
__global__ void k_route(const float* __restrict__ x) {
    int pix = blockIdx.x * 256 + threadIdx.x;
    int b = pix / HW;
    __shared__ float wr[E*C];
    __shared__ float br[E];
    __shared__ float psum[E];
    __shared__ int   scnt[E], sbase[E];
    for (int i = threadIdx.x; i < E*C; i += 256) wr[i] = g_Wr[b*E*C + i];
    if (threadIdx.x < E) {
        br[threadIdx.x] = g_br[b*E + threadIdx.x];
        psum[threadIdx.x] = 0.f;
        scnt[threadIdx.x] = 0;
    }
    __syncthreads();

    float pr[E];
    #pragma unroll
    for (int e = 0; e < E; e++) pr[e] = br[e];
    const float* xp = x + (size_t)b*C*HW + (pix - b*HW);
    for (int c = 0; c < C; c += 4) {
        float x0 = xp[(size_t)(c+0) * HW];
        float x1 = xp[(size_t)(c+1) * HW];
        float x2 = xp[(size_t)(c+2) * HW];
        float x3 = xp[(size_t)(c+3) * HW];
        #pragma unroll
        for (int e = 0; e < E; e++) {
            float a = pr[e];
            a += x0 * wr[e*C + c + 0];
            a += x1 * wr[e*C + c + 1];
            a += x2 * wr[e*C + c + 2];
            a += x3 * wr[e*C + c + 3];
            pr[e] = a;
        }
    }
    float mx = -1e30f;
    #pragma unroll
    for (int e = 0; e < E; e++) { pr[e] *= 0.125f; mx = fmaxf(mx, pr[e]); }
    float sm = 0.f;
    #pragma unroll
    for (int e = 0; e < E; e++) { pr[e] = expf(pr[e] - mx); sm += pr[e]; }
    float invs = 1.0f / sm;
    #pragma unroll
    for (int e = 0; e < E; e++) pr[e] *= invs;

    int used = 0;
    float tsum = 0.f;
    #pragma unroll
    for (int k2 = 0; k2 < KSEL; k2++) {
        float bv = -1.f; int bi = 0;
        #pragma unroll
        for (int e = 0; e < E; e++)
            if (!((used >> e) & 1) && pr[e] > bv) { bv = pr[e]; bi = e; }
        used |= 1 << bi;
        tsum += bv;
    }
    float invt = 1.0f / tsum;

    int loc[E];
    #pragma unroll
    for (int e = 0; e < E; e++) {
        int selq = (used >> e) & 1;
        g_route[(size_t)e * NPIX + pix] = selq ? pr[e] * invt : 0.f;
        atomicAdd(&psum[e], pr[e]);
        loc[e] = selq ? atomicAdd(&scnt[e], 1) : -1;
    }
    __syncthreads();
    if (threadIdx.x < E) {
        int e = threadIdx.x;
        sbase[e] = atomicAdd(&g_cnt[e], scnt[e]);
        atomicAdd(&g_probsum[e], psum[e]);
        atomicAdd(&g_loadsum[e], (float)scnt[e]);
    }
    __syncthreads();
    #pragma unroll
    for (int e = 0; e < E; e++) {
        if (loc[e] >= 0) {
            int slot = sbase[e] + loc[e];
            g_pidx[e*NPIX + slot] = pix;
            g_slot[e*NPIX + pix]  = slot;
        }
    }
}

// ---------------- kernel C: HMMA grouped-GEMM expert MLPs ----------------
__global__ void __launch_bounds__(256, 1)
k_mlp(const float* __restrict__ x,
      const float* __restrict__ eb1,
      const float* __restrict__ eb2) {
    extern __shared__ __align__(16) __nv_bfloat16 sm[];
    __nv_bfloat16* Xh = sm;                  // [128][LDT]
    __nv_bfloat16* Wh = Xh + 128*LDT;
    __nv_bfloat16* Hh = Wh + 128*LDT;
    __shared__ int   pid[128];
    __shared__ float bias1[128], bias2[128];

    const int e     = blockIdx.y;
    const int cnt   = g_cnt[e];
    const int tile0 = blockIdx.x * 128;
    if (tile0 >= cnt) return;
    const int rem = min(128, cnt - tile0);
    const int tid = threadIdx.x;
    const int wid = tid >> 5, lane = tid & 31;

    if (tid < 128) {
        pid[tid]   = g_pidx[e*NPIX + tile0 + min(tid, rem - 1)];
        bias2[tid] = eb2[(size_t)e*C + tid];
    }
    __syncthreads();

    // gather X -> bf16 [slot][c]
    for (int idx = tid; idx < 128*128; idx += 256) {
        int slot = idx & 127, c = idx >> 7;
        int p = pid[slot];
        int b = p >> 12;
        float v = x[(size_t)b*(C-1)*HW + (size_t)c*HW + p];
        Xh[slot*LDT + c] = __float2bfloat16(v);
    }

    const __nv_bfloat16* w1h = g_w1h + (size_t)e*HID*C;
    const __nv_bfloat16* w2h = g_w2h + (size_t)e*C*HID;

    const int m0 = (wid >> 1) * 32;
    const int n0 = (wid & 1) * 64;
    const int lr = lane & 7, lq = lane >> 3;
    const int aoff = ((lr + (lq & 1)*8) * LDT + (lq >> 1)*8) * 2;
    const int boff = ((lr + (lq >> 1)*8) * LDT + (lq & 1)*8) * 2;
    const int er = lane >> 2;
    const int ec = (lane & 3) * 2;

    const uint32_t uXh = smem_u32(Xh);
    const uint32_t uWh = smem_u32(Wh);
    const uint32_t uHh = smem_u32(Hh);

    const uint32_t aXh = uXh + m0*LDT*2 + aoff;
    const uint32_t aHh = uHh + m0*LDT*2 + aoff;
    const uint32_t bWh = uWh + n0*LDT*2 + boff;

    float yacc[2][8][4];
    #pragma unroll
    for (int mt = 0; mt < 2; mt++)
        #pragma unroll
        for (int nt = 0; nt < 8; nt++)
            #pragma unroll
            for (int q = 0; q < 4; q++) yacc[mt][nt][q] = 0.f;

    for (int rc = 0; rc < 4; rc++) {
        const int r0 = rc * 128;
        __syncthreads();

        for (int idx = tid; idx < 128*16; idx += 256) {
            int row = idx >> 4, q = idx & 15;
            *reinterpret_cast<uint4*>(Wh + row*LDT + q*8) =
                *reinterpret_cast<const uint4*>(w1h + (size_t)(r0+row)*C + q*8);
        }
        if (tid < 128) bias1[tid] = eb1[(size_t)e*HID + r0 + tid];
        __syncthreads();

        // ---- GEMM1
        float h[2][8][4];
        #pragma unroll
        for (int mt = 0; mt < 2; mt++)
            #pragma unroll
            for (int nt = 0; nt < 8; nt++)
                #pragma unroll
                for (int q = 0; q < 4; q++) h[mt][nt][q] = 0.f;

        #pragma unroll 2
        for (int ks2 = 0; ks2 < 8; ks2++) {
            const uint32_t kb = ks2 * 32;
            uint32_t ah[2][4];
            ldsm4(aXh + kb,             ah[0]);
            ldsm4(aXh + kb + 16*LDT*2,  ah[1]);
            #pragma unroll
            for (int ntp = 0; ntp < 4; ntp++) {
                uint32_t bh[4];
                ldsm4(bWh + ntp*16*LDT*2 + kb, bh);
                #pragma unroll
                for (int mt = 0; mt < 2; mt++) {
                    mma16816(h[mt][ntp*2],   ah[mt], bh);
                    mma16816(h[mt][ntp*2+1], ah[mt], bh + 2);
                }
            }
        }

        // ---- gelu + bias -> Hh
        #pragma unroll
        for (int mt = 0; mt < 2; mt++) {
            #pragma unroll
            for (int nt = 0; nt < 8; nt++) {
                int gm = m0 + mt*16 + er;
                int gn = n0 + nt*8 + ec;
                float b1a = bias1[gn], b1b = bias1[gn+1];
                float u0 = h[mt][nt][0] + b1a;
                float u1 = h[mt][nt][1] + b1b;
                float u2 = h[mt][nt][2] + b1a;
                float u3 = h[mt][nt][3] + b1b;
                u0 = 0.5f*u0*(1.0f + erff(u0*0.70710678118654752f));
                u1 = 0.5f*u1*(1.0f + erff(u1*0.70710678118654752f));
                u2 = 0.5f*u2*(1.0f + erff(u2*0.70710678118654752f));
                u3 = 0.5f*u3*(1.0f + erff(u3*0.70710678118654752f));
                *reinterpret_cast<uint32_t*>(Hh + gm*LDT + gn)     = pack_bf2(u0, u1);
                *reinterpret_cast<uint32_t*>(Hh + (gm+8)*LDT + gn) = pack_bf2(u2, u3);
            }
        }
        __syncthreads();

        for (int idx = tid; idx < 128*16; idx += 256) {
            int row = idx >> 4, q = idx & 15;
            *reinterpret_cast<uint4*>(Wh + row*LDT + q*8) =
                *reinterpret_cast<const uint4*>(w2h + (size_t)row*HID + r0 + q*8);
        }
        __syncthreads();

        // ---- GEMM2
        #pragma unroll 2
        for (int ks2 = 0; ks2 < 8; ks2++) {
            const uint32_t kb = ks2 * 32;
            uint32_t ah[2][4];
            ldsm4(aHh + kb,            ah[0]);
            ldsm4(aHh + kb + 16*LDT*2, ah[1]);
            #pragma unroll
            for (int ntp = 0; ntp < 4; ntp++) {
                uint32_t bh[4];
                ldsm4(bWh + ntp*16*LDT*2 + kb, bh);
                #pragma unroll
                for (int mt = 0; mt < 2; mt++) {
                    mma16816(yacc[mt][ntp*2],   ah[mt], bh);
                    mma16816(yacc[mt][ntp*2+1], ah[mt], bh + 2);
                }
            }
        }
    }

    // ---- epilogue
    #pragma unroll
    for (int mt = 0; mt < 2; mt++) {
        #pragma unroll
        for (int nt = 0; nt < 8; nt++) {
            int slot = m0 + mt*16 + er;
            int cc   = n0 + nt*8 + ec;
            float b2a = bias2[cc], b2b = bias2[cc+1];
            if (slot < rem) {
                float2 o = { yacc[mt][nt][0] + b2a, yacc[mt][nt][1] + b2b };
                *reinterpret_cast<float2*>(
                    g_ybuf + ((size_t)e*NPIX + tile0 + slot)*C + cc) = o;
            }
            if (slot + 8 < rem) {
                float2 o = { yacc[mt][nt][2] + b2a, yacc[mt][nt][3] + b2b };
                *reinterpret_cast<float2*>(
                    g_ybuf + ((size_t)e*NPIX + tile0 + slot + 8)*C + cc) = o;
            }
        }
    }
}

// ---------------- kernel G: weighted gather + residual ------------------
__global__ void k_gather(const float* __restrict__ x, float* __restrict__ out) {
    __shared__ float tile[C*33];
    const int t = threadIdx.x;
    const int lane = t & 31, w = t >> 5;
    const int pix0 = blockIdx.x * 32;
    const int b = pix0 >> 12;

    #pragma unroll
    for (int k = 0; k < 4; k++) {
        int px  = w*4 + k;
        int pix = pix0 + px;
        float a0 = 0.f, a1 = 0.f, a2 = 0.f, a3 = 0.f;
        #pragma unroll
        for (int e = 0; e < E; e++) {
            float wv = g_route[(size_t)e*NPIX + pix];
            if (wv > 0.f) {
                int sl = g_slot[e*NPIX + pix];
                const float* row = g_ybuf + ((size_t)e*NPIX + sl)*C;
                a0 += wv * row[lane];
                a1 += wv * row[lane + 32];
                a2 += wv * row[lane + 64];
                a3 += wv * row[lane + 96];
            }
        }
        tile[(lane)*33 + px]      = a0;
        tile[(lane+32)*33 + px]   = a1;
        tile[(lane+64)*33 + px]   = a2;
        tile[(lane+96)*33 + px]   = a3;
    }
    __syncthreads();
    const size_t base = (size_t)b*(C-1)*HW + pix0;
    for (int idx = t; idx < C*32; idx += 256) {
        int c = idx >> 5, px = idx & 31;
        size_t a = base + (size_t)c*HW + px;
        out[a] = x[a] + tile[c*33 + px];
    }
}

// ---------------- kernel D: aux scalar -----------------------------------
__global__ void k_aux(const float* __restrict__ proto, float* __restrict__ out, int out_size) {
    __shared__ float pn[E][P];
    __shared__ float red[128];
    int t = threadIdx.x;
    if (t < E) {
        float s = 0.f;
        for (int p = 0; p < P; p++) { float v = proto[t*P + p]; s += v*v; }
        float inv = 1.0f / sqrtf(s);
        for (int p = 0; p < P; p++) pn[t][p] = proto[t*P + p] * inv;
    }
    __syncthreads();
    float s = 0.f;
    for (int idx = t; idx < E*E; idx += 128) {
        int i = idx / E, j = idx % E;
        float d = 0.f;
        for (int p = 0; p < P; p++) d += pn[i][p] * pn[j][p];
        d -= (i == j) ? 1.0f : 0.0f;
        s += d*d;
    }
    red[t] = s;
    __syncthreads();
    for (int st = 64; st; st >>= 1) { if (t < st) red[t] += red[t + st]; __syncthreads(); }
    if (t == 0) {
        float ortho = sqrtf(red[0]);
        float aux = 0.f;
        for (int e = 0; e < E; e++)
            aux += (g_probsum[e] * (1.0f/NPIX)) * (g_loadsum[e] * (1.0f/NPIX));
        aux *= (float)E;
        if (out_size > BB*C*HW) out[BB*C*HW] = aux + 0.5f * ortho;
    }
}

// ---------------- launcher ------------------------------------------------
extern "C" void kernel_launch(void* const* d_in, const int* in_sizes, int n_in,
                              void* d_out, int out_size) {
    const float* x      = (const float*)d_in[0];
    const float* proto  = (const float*)d_in[1];
    const float* ctx_w  = (const float*)d_in[2];
    const float* ctx_b  = (const float*)d_in[3];
    const float* inp_w  = (const float*)d_in[4];
    const float* inp_b  = (const float*)d_in[5];
    const float* wq     = (const float*)d_in[6];
    const float* bq     = (const float*)d_in[7];
    const float* wk     = (const float*)d_in[8];
    const float* bk     = (const float*)d_in[9];
    const float* wv     = (const float*)d_in[10];
    const float* bv     = (const float*)d_in[11];
    const float* wo     = (const float*)d_in[12];
    const float* bo     = (const float*)d_in[13];
    const float* ln_g   = (const float*)d_in[14];
    const float* ln_b   = (const float*)d_in[15];
    const float* ew1    = (const float*)d_in[16];
    const float* eb1    = (const float*)d_in[17];
    const float* ew2    = (const float*)d_in[18];
    const float* eb2    = (const float*)d_in[19];
    float* out = (float*)d_out;

    const int smem_mlp  = 3 * 128 * LDT * (int)sizeof(__nv_bfloat16);  // 104448 B
    const int smem_attn = (4*P*P + 2*P*C) * (int)sizeof(float);        // 131072 B
    cudaFuncSetAttribute(k_mlp,  cudaFuncAttributeMaxDynamicSharedMemorySize, smem_mlp);
    cudaFuncSetAttribute(k_attn, cudaFuncAttributeMaxDynamicSharedMemorySize, smem_attn);

    k_cvt<<<(E*HID*C + 255)/256, 256>>>(ew1, ew2);
    k_gc<<<BB*C, 128>>>(x);
    k_attn<<<BB, 256, smem_attn>>>(proto, ctx_w, ctx_b, inp_w, inp_b,
                                   wq, bq, wk, bk, wv, bv, wo, bo, ln_g, ln_b);
    k_route<<<NPIX/256, 256>>>(x);
    k_mlp<<<dim3(NPIX/128, E), 256, smem_mlp>>>(x, eb1, eb2);
    k_gather<<<NPIX/32, 256>>>(x, out);
    k_aux<<<1, 128>>>(proto, out, out_size);
}

// round 13
// speedup vs baseline: 1.1710x; 1.0762x over previous
#include <cuda_runtime.h>
#include <cuda_bf16.h>
#include <math.h>
#include <stdint.h>

#define E    11
#define KSEL 6
#define P    64
#define NH   4
#define HD   16
#define SEQ  12
#define BB   8
#define C    128
#define HH   64
#define WW   64
#define HW   (HH*WW)        /* 4096  */
#define NPIX (BB*HW)        /* 32768 */
#define HID  512
#define LDT  136            /* smem tile row stride in bf16 (272B = 17*16B, conflict-free) */

// ---------------- device scratch (no allocation allowed) ----------------
__device__ float g_gc[BB*C];
__device__ float g_Wr[BB*E*C];
__device__ float g_br[BB*E];
__device__ float g_route[E*NPIX];
__device__ float g_probsum[E];
__device__ float g_loadsum[E];
__device__ int   g_cnt[E];
__device__ int   g_pidx[E*NPIX];   // [e][slot] -> pixel
__device__ int   g_slot[E*NPIX];   // [e][pixel] -> slot
__device__ float g_ybuf[E*NPIX*C]; // [e][slot][c]
__device__ __align__(16) __nv_bfloat16 g_w1h[E*HID*C];  // [e][r][c]
__device__ __align__(16) __nv_bfloat16 g_w2h[E*C*HID];  // [e][c][j]

// ---------------- mma/ldmatrix helpers (sm_80-era, no 'a' gating) --------
__device__ __forceinline__ uint32_t smem_u32(const void* p) {
    uint32_t a;
    asm("{ .reg .u64 t; cvta.to.shared.u64 t, %1; cvt.u32.u64 %0, t; }"
        : "=r"(a) : "l"(p));
    return a;
}
__device__ __forceinline__ void ldsm4(uint32_t a, uint32_t* r) {
    asm volatile("ldmatrix.sync.aligned.m8n8.x4.shared.b16 {%0,%1,%2,%3}, [%4];"
        : "=r"(r[0]), "=r"(r[1]), "=r"(r[2]), "=r"(r[3]) : "r"(a));
}
__device__ __forceinline__ void mma16816(float* c, const uint32_t* a, const uint32_t* b) {
    asm volatile("mma.sync.aligned.m16n8k16.row.col.f32.bf16.bf16.f32 "
        "{%0,%1,%2,%3}, {%4,%5,%6,%7}, {%8,%9}, {%0,%1,%2,%3};"
        : "+f"(c[0]), "+f"(c[1]), "+f"(c[2]), "+f"(c[3])
        : "r"(a[0]), "r"(a[1]), "r"(a[2]), "r"(a[3]), "r"(b[0]), "r"(b[1]));
}
__device__ __forceinline__ uint32_t pack_bf2(float x, float y) {
    __nv_bfloat162 v = __floats2bfloat162_rn(x, y);
    return *reinterpret_cast<uint32_t*>(&v);
}

// ---------------- prep: convert weights to bf16 ---------------------------
__global__ void k_cvt(const float* __restrict__ ew1, const float* __restrict__ ew2) {
    int i = blockIdx.x * 256 + threadIdx.x;
    if (i < E*HID*C) {
        g_w1h[i] = __float2bfloat16(ew1[i]);
        g_w2h[i] = __float2bfloat16(ew2[i]);
    }
}

// ---------------- kernel 0: global-context means + zero counters --------
__global__ void k_gc(const float* __restrict__ x) {
    int bc = blockIdx.x;
    const float4* src = reinterpret_cast<const float4*>(x + (size_t)bc * HW);
    float s = 0.f;
    for (int i = threadIdx.x; i < HW/4; i += 128) {
        float4 v = src[i];
        s += v.x + v.y + v.z + v.w;
    }
    __shared__ float red[4];
    for (int o = 16; o; o >>= 1) s += __shfl_down_sync(0xffffffffu, s, o);
    if ((threadIdx.x & 31) == 0) red[threadIdx.x >> 5] = s;
    __syncthreads();
    if (threadIdx.x == 0) {
        float t = red[0] + red[1] + red[2] + red[3];
        g_gc[bc] = t * (1.0f / HW);
    }
    if (bc == 0 && threadIdx.x < E) {
        g_probsum[threadIdx.x] = 0.f;
        g_loadsum[threadIdx.x] = 0.f;
        g_cnt[threadIdx.x] = 0;
    }
}

// ---------------- kernel A: attention path + router weight folding ------
__global__ void k_attn(const float* __restrict__ proto,
                       const float* __restrict__ ctx_w, const float* __restrict__ ctx_b,
                       const float* __restrict__ inp_w, const float* __restrict__ inp_b,
                       const float* __restrict__ wq, const float* __restrict__ bq,
                       const float* __restrict__ wk, const float* __restrict__ bk,
                       const float* __restrict__ wv, const float* __restrict__ bv,
                       const float* __restrict__ wo, const float* __restrict__ bo,
                       const float* __restrict__ ln_g, const float* __restrict__ ln_b) {
    extern __shared__ float wsm[];
    float* swq  = wsm;               // P*P = 4096
    float* swk  = swq + P*P;
    float* swv  = swk + P*P;
    float* swo  = swv + P*P;
    float* sctx = swo + P*P;         // P*C = 8192
    float* sinp = sctx + P*C;        // P*C = 8192

    int b = blockIdx.x;
    int t = threadIdx.x;                       // 256 threads
    __shared__ float seq[SEQ][P], qs[SEQ][P], ks[SEQ][P], vs[SEQ][P], ao[SEQ][P], o2[SEQ][P];
    __shared__ float gx[C];
    __shared__ float mstat[SEQ], istat[SEQ];

    {
        const float4* s4;
        float4* d4;
        s4 = reinterpret_cast<const float4*>(wq);  d4 = reinterpret_cast<float4*>(swq);
        for (int i = t; i < P*P/4; i += 256) d4[i] = s4[i];
        s4 = reinterpret_cast<const float4*>(wk);  d4 = reinterpret_cast<float4*>(swk);
        for (int i = t; i < P*P/4; i += 256) d4[i] = s4[i];
        s4 = reinterpret_cast<const float4*>(wv);  d4 = reinterpret_cast<float4*>(swv);
        for (int i = t; i < P*P/4; i += 256) d4[i] = s4[i];
        s4 = reinterpret_cast<const float4*>(wo);  d4 = reinterpret_cast<float4*>(swo);
        for (int i = t; i < P*P/4; i += 256) d4[i] = s4[i];
        s4 = reinterpret_cast<const float4*>(ctx_w); d4 = reinterpret_cast<float4*>(sctx);
        for (int i = t; i < P*C/4; i += 256) d4[i] = s4[i];
        s4 = reinterpret_cast<const float4*>(inp_w); d4 = reinterpret_cast<float4*>(sinp);
        for (int i = t; i < P*C/4; i += 256) d4[i] = s4[i];
    }
    if (t < C) gx[t] = g_gc[b*C + t];
    __syncthreads();

    if (t < P) {
        float a = ctx_b[t];
        for (int c = 0; c < C; c++) a += gx[c] * sctx[t*C + c];
        seq[0][t] = a;
    }
    for (int z = t; z < E*P; z += 256) seq[1 + z/P][z%P] = proto[z];
    __syncthreads();

    for (int z = t; z < SEQ*P; z += 256) {
        int s = z >> 6, p = z & 63;
        float aq = bq[p], ak = bk[p], av = bv[p];
        for (int q = 0; q < P; q++) {
            float sv = seq[s][q];
            aq += sv * swq[p*P + q];
            ak += sv * swk[p*P + q];
            av += sv * swv[p*P + q];
        }
        qs[s][p] = aq; ks[s][p] = ak; vs[s][p] = av;
    }
    __syncthreads();

    if (t < NH*SEQ) {
        int n = t / SEQ, i = t % SEQ;
        float sc[SEQ];
        float mx = -1e30f;
        for (int j = 0; j < SEQ; j++) {
            float a = 0.f;
            for (int d = 0; d < HD; d++) a += qs[i][n*HD + d] * ks[j][n*HD + d];
            a *= 0.25f;
            sc[j] = a; mx = fmaxf(mx, a);
        }
        float sm = 0.f;
        for (int j = 0; j < SEQ; j++) { sc[j] = expf(sc[j] - mx); sm += sc[j]; }
        float inv = 1.0f / sm;
        for (int d = 0; d < HD; d++) {
            float a = 0.f;
            for (int j = 0; j < SEQ; j++) a += sc[j] * vs[j][n*HD + d];
            ao[i][n*HD + d] = a * inv;
        }
    }
    __syncthreads();

    for (int z = t; z < SEQ*P; z += 256) {
        int s = z >> 6, p = z & 63;
        float a = bo[p];
        for (int q = 0; q < P; q++) a += ao[s][q] * swo[p*P + q];
        o2[s][p] = a + seq[s][p];
    }
    __syncthreads();

    if (t < SEQ) {
        float m = 0.f;
        for (int p = 0; p < P; p++) m += o2[t][p];
        m *= (1.0f / P);
        float v = 0.f;
        for (int p = 0; p < P; p++) { float d = o2[t][p] - m; v += d*d; }
        v *= (1.0f / P);
        mstat[t] = m; istat[t] = 1.0f / sqrtf(v + 1e-5f);
    }
    __syncthreads();

    for (int z = t; z < E*P; z += 256) {
        int s = z / P + 1, p = z % P;
        seq[s][p] = (o2[s][p] - mstat[s]) * istat[s] * ln_g[p] + ln_b[p];
    }
    __syncthreads();

    for (int z = t; z < E*C; z += 256) {
        int e = z / C, c = z % C;
        float a = 0.f;
        for (int p = 0; p < P; p++) a += seq[e+1][p] * sinp[p*C + c];
        g_Wr[(b*E + e)*C + c] = a;
    }
    if (t < E) {
        float a = 0.f;
        for (int p = 0; p < P; p++) a += seq[t+1][p] * inp_b[p];
        g_br[b*E + t] = a;
    }
}

// ---------------- kernel B: routing + per-expert compaction -------------
// 512 blocks x 256 threads; 64 pixels/block; 4 threads per pixel (c-slices),
// partials reduced through smem; threads 0..63 do softmax/topk/compaction.
__global__ void k_route(const float* __restrict__ x) {
    const int t = threadIdx.x;
    const int p = t & 63;                  // pixel within block
    const int j = t >> 6;                  // c-slice 0..3
    const int pix0 = blockIdx.x * 64;
    const int b = pix0 / HW;               // 64 | 4096 -> whole block same batch
    const int pix = pix0 + p;

    __shared__ float wr[E*C];
    __shared__ float br[E];
    __shared__ float part[4][64*13];       // stride 13: conflict-free
    __shared__ float psum[E];
    __shared__ int   scnt[E], sbase[E];

    for (int i = t; i < E*C; i += 256) wr[i] = g_Wr[b*E*C + i];
    if (t < E) {
        br[t] = g_br[b*E + t];
        psum[t] = 0.f;
        scnt[t] = 0;
    }
    __syncthreads();

    // partial logits over c-slice j
    {
        float pr[E];
        #pragma unroll
        for (int e = 0; e < E; e++) pr[e] = 0.f;
        const float* xp = x + (size_t)b*C*HW + (pix - b*HW);
        for (int ci = 0; ci < 32; ci++) {
            int c = j*32 + ci;
            float xv = xp[(size_t)c * HW];
            #pragma unroll
            for (int e = 0; e < E; e++) pr[e] += xv * wr[e*C + c];
        }
        #pragma unroll
        for (int e = 0; e < E; e++) part[j][p*13 + e] = pr[e];
    }
    __syncthreads();

    int loc[E];
    if (t < 64) {
        float pr[E];
        #pragma unroll
        for (int e = 0; e < E; e++)
            pr[e] = br[e] + part[0][t*13 + e] + part[1][t*13 + e]
                          + part[2][t*13 + e] + part[3][t*13 + e];

        float mx = -1e30f;
        #pragma unroll
        for (int e = 0; e < E; e++) { pr[e] *= 0.125f; mx = fmaxf(mx, pr[e]); }
        float sm = 0.f;
        #pragma unroll
        for (int e = 0; e < E; e++) { pr[e] = expf(pr[e] - mx); sm += pr[e]; }
        float invs = 1.0f / sm;
        #pragma unroll
        for (int e = 0; e < E; e++) pr[e] *= invs;

        int used = 0;
        float tsum = 0.f;
        #pragma unroll
        for (int k2 = 0; k2 < KSEL; k2++) {
            float bv = -1.f; int bi = 0;
            #pragma unroll
            for (int e = 0; e < E; e++)
                if (!((used >> e) & 1) && pr[e] > bv) { bv = pr[e]; bi = e; }
            used |= 1 << bi;
            tsum += bv;
        }
        float invt = 1.0f / tsum;

        #pragma unroll
        for (int e = 0; e < E; e++) {
            int selq = (used >> e) & 1;
            g_route[(size_t)e * NPIX + pix] = selq ? pr[e] * invt : 0.f;
            atomicAdd(&psum[e], pr[e]);
            loc[e] = selq ? atomicAdd(&scnt[e], 1) : -1;
        }
    }
    __syncthreads();
    if (t < E) {
        sbase[t] = atomicAdd(&g_cnt[t], scnt[t]);
        atomicAdd(&g_probsum[t], psum[t]);
        atomicAdd(&g_loadsum[t], (float)scnt[t]);
    }
    __syncthreads();
    if (t < 64) {
        #pragma unroll
        for (int e = 0; e < E; e++) {
            if (loc[e] >= 0) {
                int slot = sbase[e] + loc[e];
                g_pidx[e*NPIX + slot] = pix;
                g_slot[e*NPIX + pix]  = slot;
            }
        }
    }
}

// ---------------- kernel C: HMMA grouped-GEMM expert MLPs ----------------
__global__ void __launch_bounds__(256, 1)
k_mlp(const float* __restrict__ x,
      const float* __restrict__ eb1,
      const float* __restrict__ eb2) {
    extern __shared__ __align__(16) __nv_bfloat16 sm[];
    __nv_bfloat16* Xh = sm;                  // [128][LDT]
    __nv_bfloat16* Wh = Xh + 128*LDT;
    __nv_bfloat16* Hh = Wh + 128*LDT;
    __shared__ int   pid[128];
    __shared__ float bias1[128], bias2[128];

    const int e     = blockIdx.y;
    const int cnt   = g_cnt[e];
    const int tile0 = blockIdx.x * 128;
    if (tile0 >= cnt) return;
    const int rem = min(128, cnt - tile0);
    const int tid = threadIdx.x;
    const int wid = tid >> 5, lane = tid & 31;

    if (tid < 128) {
        pid[tid]   = g_pidx[e*NPIX + tile0 + min(tid, rem - 1)];
        bias2[tid] = eb2[(size_t)e*C + tid];
    }
    __syncthreads();

    // gather X -> bf16 [slot][c]
    for (int idx = tid; idx < 128*128; idx += 256) {
        int slot = idx & 127, c = idx >> 7;
        int p = pid[slot];
        int b = p >> 12;
        float v = x[(size_t)b*(C-1)*HW + (size_t)c*HW + p];
        Xh[slot*LDT + c] = __float2bfloat16(v);
    }

    const __nv_bfloat16* w1h = g_w1h + (size_t)e*HID*C;
    const __nv_bfloat16* w2h = g_w2h + (size_t)e*C*HID;

    const int m0 = (wid >> 1) * 32;
    const int n0 = (wid & 1) * 64;
    const int lr = lane & 7, lq = lane >> 3;
    const int aoff = ((lr + (lq & 1)*8) * LDT + (lq >> 1)*8) * 2;
    const int boff = ((lr + (lq >> 1)*8) * LDT + (lq & 1)*8) * 2;
    const int er = lane >> 2;
    const int ec = (lane & 3) * 2;

    const uint32_t uXh = smem_u32(Xh);
    const uint32_t uWh = smem_u32(Wh);
    const uint32_t uHh = smem_u32(Hh);

    const uint32_t aXh = uXh + m0*LDT*2 + aoff;
    const uint32_t aHh = uHh + m0*LDT*2 + aoff;
    const uint32_t bWh = uWh + n0*LDT*2 + boff;

    float yacc[2][8][4];
    #pragma unroll
    for (int mt = 0; mt < 2; mt++)
        #pragma unroll
        for (int nt = 0; nt < 8; nt++)
            #pragma unroll
            for (int q = 0; q < 4; q++) yacc[mt][nt][q] = 0.f;

    for (int rc = 0; rc < 4; rc++) {
        const int r0 = rc * 128;
        __syncthreads();

        for (int idx = tid; idx < 128*16; idx += 256) {
            int row = idx >> 4, q = idx & 15;
            *reinterpret_cast<uint4*>(Wh + row*LDT + q*8) =
                *reinterpret_cast<const uint4*>(w1h + (size_t)(r0+row)*C + q*8);
        }
        if (tid < 128) bias1[tid] = eb1[(size_t)e*HID + r0 + tid];
        __syncthreads();

        // ---- GEMM1
        float h[2][8][4];
        #pragma unroll
        for (int mt = 0; mt < 2; mt++)
            #pragma unroll
            for (int nt = 0; nt < 8; nt++)
                #pragma unroll
                for (int q = 0; q < 4; q++) h[mt][nt][q] = 0.f;

        #pragma unroll 2
        for (int ks2 = 0; ks2 < 8; ks2++) {
            const uint32_t kb = ks2 * 32;
            uint32_t ah[2][4];
            ldsm4(aXh + kb,             ah[0]);
            ldsm4(aXh + kb + 16*LDT*2,  ah[1]);
            #pragma unroll
            for (int ntp = 0; ntp < 4; ntp++) {
                uint32_t bh[4];
                ldsm4(bWh + ntp*16*LDT*2 + kb, bh);
                #pragma unroll
                for (int mt = 0; mt < 2; mt++) {
                    mma16816(h[mt][ntp*2],   ah[mt], bh);
                    mma16816(h[mt][ntp*2+1], ah[mt], bh + 2);
                }
            }
        }

        // ---- gelu + bias -> Hh
        #pragma unroll
        for (int mt = 0; mt < 2; mt++) {
            #pragma unroll
            for (int nt = 0; nt < 8; nt++) {
                int gm = m0 + mt*16 + er;
                int gn = n0 + nt*8 + ec;
                float b1a = bias1[gn], b1b = bias1[gn+1];
                float u0 = h[mt][nt][0] + b1a;
                float u1 = h[mt][nt][1] + b1b;
                float u2 = h[mt][nt][2] + b1a;
                float u3 = h[mt][nt][3] + b1b;
                u0 = 0.5f*u0*(1.0f + erff(u0*0.70710678118654752f));
                u1 = 0.5f*u1*(1.0f + erff(u1*0.70710678118654752f));
                u2 = 0.5f*u2*(1.0f + erff(u2*0.70710678118654752f));
                u3 = 0.5f*u3*(1.0f + erff(u3*0.70710678118654752f));
                *reinterpret_cast<uint32_t*>(Hh + gm*LDT + gn)     = pack_bf2(u0, u1);
                *reinterpret_cast<uint32_t*>(Hh + (gm+8)*LDT + gn) = pack_bf2(u2, u3);
            }
        }
        __syncthreads();

        for (int idx = tid; idx < 128*16; idx += 256) {
            int row = idx >> 4, q = idx & 15;
            *reinterpret_cast<uint4*>(Wh + row*LDT + q*8) =
                *reinterpret_cast<const uint4*>(w2h + (size_t)row*HID + r0 + q*8);
        }
        __syncthreads();

        // ---- GEMM2
        #pragma unroll 2
        for (int ks2 = 0; ks2 < 8; ks2++) {
            const uint32_t kb = ks2 * 32;
            uint32_t ah[2][4];
            ldsm4(aHh + kb,            ah[0]);
            ldsm4(aHh + kb + 16*LDT*2, ah[1]);
            #pragma unroll
            for (int ntp = 0; ntp < 4; ntp++) {
                uint32_t bh[4];
                ldsm4(bWh + ntp*16*LDT*2 + kb, bh);
                #pragma unroll
                for (int mt = 0; mt < 2; mt++) {
                    mma16816(yacc[mt][ntp*2],   ah[mt], bh);
                    mma16816(yacc[mt][ntp*2+1], ah[mt], bh + 2);
                }
            }
        }
    }

    // ---- epilogue
    #pragma unroll
    for (int mt = 0; mt < 2; mt++) {
        #pragma unroll
        for (int nt = 0; nt < 8; nt++) {
            int slot = m0 + mt*16 + er;
            int cc   = n0 + nt*8 + ec;
            float b2a = bias2[cc], b2b = bias2[cc+1];
            if (slot < rem) {
                float2 o = { yacc[mt][nt][0] + b2a, yacc[mt][nt][1] + b2b };
                *reinterpret_cast<float2*>(
                    g_ybuf + ((size_t)e*NPIX + tile0 + slot)*C + cc) = o;
            }
            if (slot + 8 < rem) {
                float2 o = { yacc[mt][nt][2] + b2a, yacc[mt][nt][3] + b2b };
                *reinterpret_cast<float2*>(
                    g_ybuf + ((size_t)e*NPIX + tile0 + slot + 8)*C + cc) = o;
            }
        }
    }
}

// ---------------- kernel G: weighted gather + residual ------------------
__global__ void k_gather(const float* __restrict__ x, float* __restrict__ out) {
    __shared__ float tile[C*33];
    const int t = threadIdx.x;
    const int lane = t & 31, w = t >> 5;
    const int pix0 = blockIdx.x * 32;
    const int b = pix0 >> 12;

    #pragma unroll
    for (int k = 0; k < 4; k++) {
        int px  = w*4 + k;
        int pix = pix0 + px;
        float a0 = 0.f, a1 = 0.f, a2 = 0.f, a3 = 0.f;
        #pragma unroll
        for (int e = 0; e < E; e++) {
            float wv = g_route[(size_t)e*NPIX + pix];
            if (wv > 0.f) {
                int sl = g_slot[e*NPIX + pix];
                const float* row = g_ybuf + ((size_t)e*NPIX + sl)*C;
                a0 += wv * row[lane];
                a1 += wv * row[lane + 32];
                a2 += wv * row[lane + 64];
                a3 += wv * row[lane + 96];
            }
        }
        tile[(lane)*33 + px]      = a0;
        tile[(lane+32)*33 + px]   = a1;
        tile[(lane+64)*33 + px]   = a2;
        tile[(lane+96)*33 + px]   = a3;
    }
    __syncthreads();
    const size_t base = (size_t)b*(C-1)*HW + pix0;
    for (int idx = t; idx < C*32; idx += 256) {
        int c = idx >> 5, px = idx & 31;
        size_t a = base + (size_t)c*HW + px;
        out[a] = x[a] + tile[c*33 + px];
    }
}

// ---------------- kernel D: aux scalar -----------------------------------
__global__ void k_aux(const float* __restrict__ proto, float* __restrict__ out, int out_size) {
    __shared__ float pn[E][P];
    __shared__ float red[128];
    int t = threadIdx.x;
    if (t < E) {
        float s = 0.f;
        for (int p = 0; p < P; p++) { float v = proto[t*P + p]; s += v*v; }
        float inv = 1.0f / sqrtf(s);
        for (int p = 0; p < P; p++) pn[t][p] = proto[t*P + p] * inv;
    }
    __syncthreads();
    float s = 0.f;
    for (int idx = t; idx < E*E; idx += 128) {
        int i = idx / E, j = idx % E;
        float d = 0.f;
        for (int p = 0; p < P; p++) d += pn[i][p] * pn[j][p];
        d -= (i == j) ? 1.0f : 0.0f;
        s += d*d;
    }
    red[t] = s;
    __syncthreads();
    for (int st = 64; st; st >>= 1) { if (t < st) red[t] += red[t + st]; __syncthreads(); }
    if (t == 0) {
        float ortho = sqrtf(red[0]);
        float aux = 0.f;
        for (int e = 0; e < E; e++)
            aux += (g_probsum[e] * (1.0f/NPIX)) * (g_loadsum[e] * (1.0f/NPIX));
        aux *= (float)E;
        if (out_size > BB*C*HW) out[BB*C*HW] = aux + 0.5f * ortho;
    }
}

// ---------------- launcher ------------------------------------------------
extern "C" void kernel_launch(void* const* d_in, const int* in_sizes, int n_in,
                              void* d_out, int out_size) {
    const float* x      = (const float*)d_in[0];
    const float* proto  = (const float*)d_in[1];
    const float* ctx_w  = (const float*)d_in[2];
    const float* ctx_b  = (const float*)d_in[3];
    const float* inp_w  = (const float*)d_in[4];
    const float* inp_b  = (const float*)d_in[5];
    const float* wq     = (const float*)d_in[6];
    const float* bq     = (const float*)d_in[7];
    const float* wk     = (const float*)d_in[8];
    const float* bk     = (const float*)d_in[9];
    const float* wv     = (const float*)d_in[10];
    const float* bv     = (const float*)d_in[11];
    const float* wo     = (const float*)d_in[12];
    const float* bo     = (const float*)d_in[13];
    const float* ln_g   = (const float*)d_in[14];
    const float* ln_b   = (const float*)d_in[15];
    const float* ew1    = (const float*)d_in[16];
    const float* eb1    = (const float*)d_in[17];
    const float* ew2    = (const float*)d_in[18];
    const float* eb2    = (const float*)d_in[19];
    float* out = (float*)d_out;

    const int smem_mlp  = 3 * 128 * LDT * (int)sizeof(__nv_bfloat16);  // 104448 B
    const int smem_attn = (4*P*P + 2*P*C) * (int)sizeof(float);        // 131072 B
    cudaFuncSetAttribute(k_mlp,  cudaFuncAttributeMaxDynamicSharedMemorySize, smem_mlp);
    cudaFuncSetAttribute(k_attn, cudaFuncAttributeMaxDynamicSharedMemorySize, smem_attn);

    k_cvt<<<(E*HID*C + 255)/256, 256>>>(ew1, ew2);
    k_gc<<<BB*C, 128>>>(x);
    k_attn<<<BB, 256, smem_attn>>>(proto, ctx_w, ctx_b, inp_w, inp_b,
                                   wq, bq, wk, bk, wv, bv, wo, bo, ln_g, ln_b);
    k_route<<<NPIX/64, 256>>>(x);
    k_mlp<<<dim3(NPIX/128, E), 256, smem_mlp>>>(x, eb1, eb2);
    k_gather<<<NPIX/32, 256>>>(x, out);
    k_aux<<<1, 128>>>(proto, out, out_size);
}

// round 14
// speedup vs baseline: 1.2197x; 1.0416x over previous
#include <cuda_runtime.h>
#include <cuda_bf16.h>
#include <math.h>
#include <stdint.h>

#define E    11
#define KSEL 6
#define P    64
#define NH   4
#define HD   16
#define SEQ  12
#define BB   8
#define C    128
#define HH   64
#define WW   64
#define HW   (HH*WW)        /* 4096  */
#define NPIX (BB*HW)        /* 32768 */
#define HID  512
#define LDT  136            /* smem tile row stride in bf16 (272B = 17*16B, conflict-free) */

// ---------------- device scratch (no allocation allowed) ----------------
__device__ float g_gc[BB*C];
__device__ float g_Wr[BB*E*C];
__device__ float g_br[BB*E];
__device__ float g_route[E*NPIX];
__device__ float g_probsum[E];
__device__ float g_loadsum[E];
__device__ int   g_cnt[E];
__device__ int   g_pidx[E*NPIX];   // [e][slot] -> pixel
__device__ int   g_slot[E*NPIX];   // [e][pixel] -> slot
__device__ float g_ybuf[E*NPIX*C]; // [e][slot][c]
__device__ __align__(16) __nv_bfloat16 g_w1h[E*HID*C];  // [e][r][c]
__device__ __align__(16) __nv_bfloat16 g_w2h[E*C*HID];  // [e][c][j]

// ---------------- mma/ldmatrix helpers (sm_80-era, no 'a' gating) --------
__device__ __forceinline__ uint32_t smem_u32(const void* p) {
    uint32_t a;
    asm("{ .reg .u64 t; cvta.to.shared.u64 t, %1; cvt.u32.u64 %0, t; }"
        : "=r"(a) : "l"(p));
    return a;
}
__device__ __forceinline__ void ldsm4(uint32_t a, uint32_t* r) {
    asm volatile("ldmatrix.sync.aligned.m8n8.x4.shared.b16 {%0,%1,%2,%3}, [%4];"
        : "=r"(r[0]), "=r"(r[1]), "=r"(r[2]), "=r"(r[3]) : "r"(a));
}
__device__ __forceinline__ void mma16816(float* c, const uint32_t* a, const uint32_t* b) {
    asm volatile("mma.sync.aligned.m16n8k16.row.col.f32.bf16.bf16.f32 "
        "{%0,%1,%2,%3}, {%4,%5,%6,%7}, {%8,%9}, {%0,%1,%2,%3};"
        : "+f"(c[0]), "+f"(c[1]), "+f"(c[2]), "+f"(c[3])
        : "r"(a[0]), "r"(a[1]), "r"(a[2]), "r"(a[3]), "r"(b[0]), "r"(b[1]));
}
__device__ __forceinline__ uint32_t pack_bf2(float x, float y) {
    __nv_bfloat162 v = __floats2bfloat162_rn(x, y);
    return *reinterpret_cast<uint32_t*>(&v);
}
#define CP_ASYNC16(dst, src) \
    asm volatile("cp.async.cg.shared.global [%0], [%1], 16;" :: "r"(dst), "l"(src))
#define CP_COMMIT() asm volatile("cp.async.commit_group;" ::: "memory")
#define CP_WAIT1()  asm volatile("cp.async.wait_group 1;" ::: "memory")
#define CP_WAIT0()  asm volatile("cp.async.wait_group 0;" ::: "memory")

// ---------------- prep: convert weights to bf16 ---------------------------
__global__ void k_cvt(const float* __restrict__ ew1, const float* __restrict__ ew2) {
    int i = blockIdx.x * 256 + threadIdx.x;
    if (i < E*HID*C) {
        g_w1h[i] = __float2bfloat16(ew1[i]);
        g_w2h[i] = __float2bfloat16(ew2[i]);
    }
}

// ---------------- kernel 0: global-context means + zero counters --------
__global__ void k_gc(const float* __restrict__ x) {
    int bc = blockIdx.x;
    const float4* src = reinterpret_cast<const float4*>(x + (size_t)bc * HW);
    float s = 0.f;
    for (int i = threadIdx.x; i < HW/4; i += 128) {
        float4 v = src[i];
        s += v.x + v.y + v.z + v.w;
    }
    __shared__ float red[4];
    for (int o = 16; o; o >>= 1) s += __shfl_down_sync(0xffffffffu, s, o);
    if ((threadIdx.x & 31) == 0) red[threadIdx.x >> 5] = s;
    __syncthreads();
    if (threadIdx.x == 0) {
        float t = red[0] + red[1] + red[2] + red[3];
        g_gc[bc] = t * (1.0f / HW);
    }
    if (bc == 0 && threadIdx.x < E) {
        g_probsum[threadIdx.x] = 0.f;
        g_loadsum[threadIdx.x] = 0.f;
        g_cnt[threadIdx.x] = 0;
    }
}

// ---------------- kernel A: attention path + router weight folding ------
__global__ void k_attn(const float* __restrict__ proto,
                       const float* __restrict__ ctx_w, const float* __restrict__ ctx_b,
                       const float* __restrict__ inp_w, const float* __restrict__ inp_b,
                       const float* __restrict__ wq, const float* __restrict__ bq,
                       const float* __restrict__ wk, const float* __restrict__ bk,
                       const float* __restrict__ wv, const float* __restrict__ bv,
                       const float* __restrict__ wo, const float* __restrict__ bo,
                       const float* __restrict__ ln_g, const float* __restrict__ ln_b) {
    extern __shared__ float wsm[];
    float* swq  = wsm;               // P*P = 4096
    float* swk  = swq + P*P;
    float* swv  = swk + P*P;
    float* swo  = swv + P*P;
    float* sctx = swo + P*P;         // P*C = 8192
    float* sinp = sctx + P*C;        // P*C = 8192

    int b = blockIdx.x;
    int t = threadIdx.x;                       // 256 threads
    __shared__ float seq[SEQ][P], qs[SEQ][P], ks[SEQ][P], vs[SEQ][P], ao[SEQ][P], o2[SEQ][P];
    __shared__ float gx[C];
    __shared__ float mstat[SEQ], istat[SEQ];

    {
        const float4* s4;
        float4* d4;
        s4 = reinterpret_cast<const float4*>(wq);  d4 = reinterpret_cast<float4*>(swq);
        for (int i = t; i < P*P/4; i += 256) d4[i] = s4[i];
        s4 = reinterpret_cast<const float4*>(wk);  d4 = reinterpret_cast<float4*>(swk);
        for (int i = t; i < P*P/4; i += 256) d4[i] = s4[i];
        s4 = reinterpret_cast<const float4*>(wv);  d4 = reinterpret_cast<float4*>(swv);
        for (int i = t; i < P*P/4; i += 256) d4[i] = s4[i];
        s4 = reinterpret_cast<const float4*>(wo);  d4 = reinterpret_cast<float4*>(swo);
        for (int i = t; i < P*P/4; i += 256) d4[i] = s4[i];
        s4 = reinterpret_cast<const float4*>(ctx_w); d4 = reinterpret_cast<float4*>(sctx);
        for (int i = t; i < P*C/4; i += 256) d4[i] = s4[i];
        s4 = reinterpret_cast<const float4*>(inp_w); d4 = reinterpret_cast<float4*>(sinp);
        for (int i = t; i < P*C/4; i += 256) d4[i] = s4[i];
    }
    if (t < C) gx[t] = g_gc[b*C + t];
    __syncthreads();

    if (t < P) {
        float a = ctx_b[t];
        for (int c = 0; c < C; c++) a += gx[c] * sctx[t*C + c];
        seq[0][t] = a;
    }
    for (int z = t; z < E*P; z += 256) seq[1 + z/P][z%P] = proto[z];
    __syncthreads();

    for (int z = t; z < SEQ*P; z += 256) {
        int s = z >> 6, p = z & 63;
        float aq = bq[p], ak = bk[p], av = bv[p];
        for (int q = 0; q < P; q++) {
            float sv = seq[s][q];
            aq += sv * swq[p*P + q];
            ak += sv * swk[p*P + q];
            av += sv * swv[p*P + q];
        }
        qs[s][p] = aq; ks[s][p] = ak; vs[s][p] = av;
    }
    __syncthreads();

    if (t < NH*SEQ) {
        int n = t / SEQ, i = t % SEQ;
        float sc[SEQ];
        float mx = -1e30f;
        for (int j = 0; j < SEQ; j++) {
            float a = 0.f;
            for (int d = 0; d < HD; d++) a += qs[i][n*HD + d] * ks[j][n*HD + d];
            a *= 0.25f;
            sc[j] = a; mx = fmaxf(mx, a);
        }
        float sm = 0.f;
        for (int j = 0; j < SEQ; j++) { sc[j] = expf(sc[j] - mx); sm += sc[j]; }
        float inv = 1.0f / sm;
        for (int d = 0; d < HD; d++) {
            float a = 0.f;
            for (int j = 0; j < SEQ; j++) a += sc[j] * vs[j][n*HD + d];
            ao[i][n*HD + d] = a * inv;
        }
    }
    __syncthreads();

    for (int z = t; z < SEQ*P; z += 256) {
        int s = z >> 6, p = z & 63;
        float a = bo[p];
        for (int q = 0; q < P; q++) a += ao[s][q] * swo[p*P + q];
        o2[s][p] = a + seq[s][p];
    }
    __syncthreads();

    if (t < SEQ) {
        float m = 0.f;
        for (int p = 0; p < P; p++) m += o2[t][p];
        m *= (1.0f / P);
        float v = 0.f;
        for (int p = 0; p < P; p++) { float d = o2[t][p] - m; v += d*d; }
        v *= (1.0f / P);
        mstat[t] = m; istat[t] = 1.0f / sqrtf(v + 1e-5f);
    }
    __syncthreads();

    for (int z = t; z < E*P; z += 256) {
        int s = z / P + 1, p = z % P;
        seq[s][p] = (o2[s][p] - mstat[s]) * istat[s] * ln_g[p] + ln_b[p];
    }
    __syncthreads();

    for (int z = t; z < E*C; z += 256) {
        int e = z / C, c = z % C;
        float a = 0.f;
        for (int p = 0; p < P; p++) a += seq[e+1][p] * sinp[p*C + c];
        g_Wr[(b*E + e)*C + c] = a;
    }
    if (t < E) {
        float a = 0.f;
        for (int p = 0; p < P; p++) a += seq[t+1][p] * inp_b[p];
        g_br[b*E + t] = a;
    }
}

// ---------------- kernel B: routing + per-expert compaction -------------
// 512 blocks x 256 threads; 64 pixels/block; 4 threads per pixel (c-slices).
__global__ void k_route(const float* __restrict__ x) {
    const int t = threadIdx.x;
    const int p = t & 63;
    const int j = t >> 6;
    const int pix0 = blockIdx.x * 64;
    const int b = pix0 / HW;
    const int pix = pix0 + p;

    __shared__ float wr[E*C];
    __shared__ float br[E];
    __shared__ float part[4][64*13];
    __shared__ float psum[E];
    __shared__ int   scnt[E], sbase[E];

    for (int i = t; i < E*C; i += 256) wr[i] = g_Wr[b*E*C + i];
    if (t < E) {
        br[t] = g_br[b*E + t];
        psum[t] = 0.f;
        scnt[t] = 0;
    }
    __syncthreads();

    {
        float pr[E];
        #pragma unroll
        for (int e = 0; e < E; e++) pr[e] = 0.f;
        const float* xp = x + (size_t)b*C*HW + (pix - b*HW);
        for (int ci = 0; ci < 32; ci++) {
            int c = j*32 + ci;
            float xv = xp[(size_t)c * HW];
            #pragma unroll
            for (int e = 0; e < E; e++) pr[e] += xv * wr[e*C + c];
        }
        #pragma unroll
        for (int e = 0; e < E; e++) part[j][p*13 + e] = pr[e];
    }
    __syncthreads();

    int loc[E];
    if (t < 64) {
        float pr[E];
        #pragma unroll
        for (int e = 0; e < E; e++)
            pr[e] = br[e] + part[0][t*13 + e] + part[1][t*13 + e]
                          + part[2][t*13 + e] + part[3][t*13 + e];

        float mx = -1e30f;
        #pragma unroll
        for (int e = 0; e < E; e++) { pr[e] *= 0.125f; mx = fmaxf(mx, pr[e]); }
        float sm = 0.f;
        #pragma unroll
        for (int e = 0; e < E; e++) { pr[e] = expf(pr[e] - mx); sm += pr[e]; }
        float invs = 1.0f / sm;
        #pragma unroll
        for (int e = 0; e < E; e++) pr[e] *= invs;

        int used = 0;
        float tsum = 0.f;
        #pragma unroll
        for (int k2 = 0; k2 < KSEL; k2++) {
            float bv = -1.f; int bi = 0;
            #pragma unroll
            for (int e = 0; e < E; e++)
                if (!((used >> e) & 1) && pr[e] > bv) { bv = pr[e]; bi = e; }
            used |= 1 << bi;
            tsum += bv;
        }
        float invt = 1.0f / tsum;

        #pragma unroll
        for (int e = 0; e < E; e++) {
            int selq = (used >> e) & 1;
            g_route[(size_t)e * NPIX + pix] = selq ? pr[e] * invt : 0.f;
            atomicAdd(&psum[e], pr[e]);
            loc[e] = selq ? atomicAdd(&scnt[e], 1) : -1;
        }
    }
    __syncthreads();
    if (t < E) {
        sbase[t] = atomicAdd(&g_cnt[t], scnt[t]);
        atomicAdd(&g_probsum[t], psum[t]);
        atomicAdd(&g_loadsum[t], (float)scnt[t]);
    }
    __syncthreads();
    if (t < 64) {
        #pragma unroll
        for (int e = 0; e < E; e++) {
            if (loc[e] >= 0) {
                int slot = sbase[e] + loc[e];
                g_pidx[e*NPIX + slot] = pix;
                g_slot[e*NPIX + pix]  = slot;
            }
        }
    }
}

// ---------------- kernel C: HMMA grouped-GEMM expert MLPs ----------------
// Double-buffered cp.async weight pipeline: Wa <- W1 chunks, Wb <- W2 chunks.
__global__ void __launch_bounds__(256, 1)
k_mlp(const float* __restrict__ x,
      const float* __restrict__ eb1,
      const float* __restrict__ eb2) {
    extern __shared__ __align__(16) __nv_bfloat16 sm[];
    __nv_bfloat16* Xh = sm;                  // [128][LDT]
    __nv_bfloat16* Wa = Xh + 128*LDT;        // W1 chunk
    __nv_bfloat16* Wb = Wa + 128*LDT;        // W2 chunk
    __nv_bfloat16* Hh = Wb + 128*LDT;
    __shared__ int   pid[128];
    __shared__ float bias1[128], bias2[128];

    const int e     = blockIdx.y;
    const int cnt   = g_cnt[e];
    const int tile0 = blockIdx.x * 128;
    if (tile0 >= cnt) return;
    const int rem = min(128, cnt - tile0);
    const int tid = threadIdx.x;
    const int wid = tid >> 5, lane = tid & 31;

    const __nv_bfloat16* w1h = g_w1h + (size_t)e*HID*C;
    const __nv_bfloat16* w2h = g_w2h + (size_t)e*C*HID;

    const uint32_t uXh = smem_u32(Xh);
    const uint32_t uWa = smem_u32(Wa);
    const uint32_t uWb = smem_u32(Wb);
    const uint32_t uHh = smem_u32(Hh);

    // per-thread fill coords (8 x 16B per fill)
    const int frow0 = tid >> 1;              // rows tid/2, +128/2 per step of 2
    // we fill 2048 16B-quads with 256 threads -> 8 each; layout: idx = tid + k*256
    // idx -> row = idx>>4, q = idx&15

    // prologue: prefetch W1 chunk 0 into Wa
    #pragma unroll
    for (int k = 0; k < 8; k++) {
        int idx = tid + k*256;
        int row = idx >> 4, q = idx & 15;
        CP_ASYNC16(uWa + (uint32_t)(row*LDT + q*8)*2,
                   w1h + (size_t)row*C + q*8);
    }
    CP_COMMIT();

    if (tid < 128) {
        pid[tid]   = g_pidx[e*NPIX + tile0 + min(tid, rem - 1)];
        bias2[tid] = eb2[(size_t)e*C + tid];
    }
    __syncthreads();

    // gather X -> bf16 [slot][c]  (overlaps with W1(0) prefetch)
    for (int idx = tid; idx < 128*128; idx += 256) {
        int slot = idx & 127, c = idx >> 7;
        int p = pid[slot];
        int b = p >> 12;
        float v = x[(size_t)b*(C-1)*HW + (size_t)c*HW + p];
        Xh[slot*LDT + c] = __float2bfloat16(v);
    }

    const int m0 = (wid >> 1) * 32;
    const int n0 = (wid & 1) * 64;
    const int lr = lane & 7, lq = lane >> 3;
    const int aoff = ((lr + (lq & 1)*8) * LDT + (lq >> 1)*8) * 2;
    const int boff = ((lr + (lq >> 1)*8) * LDT + (lq & 1)*8) * 2;
    const int er = lane >> 2;
    const int ec = (lane & 3) * 2;

    const uint32_t aXh = uXh + m0*LDT*2 + aoff;
    const uint32_t aHh = uHh + m0*LDT*2 + aoff;
    const uint32_t bW1 = uWa + n0*LDT*2 + boff;
    const uint32_t bW2 = uWb + n0*LDT*2 + boff;

    float yacc[2][8][4];
    #pragma unroll
    for (int mt = 0; mt < 2; mt++)
        #pragma unroll
        for (int nt = 0; nt < 8; nt++)
            #pragma unroll
            for (int q = 0; q < 4; q++) yacc[mt][nt][q] = 0.f;

    for (int rc = 0; rc < 4; rc++) {
        const int r0 = rc * 128;

        // issue W2(rc) -> Wb ; prior iteration's GEMM2 reads of Wb are done
        // (guarded by the syncthreads at the end of the previous iteration)
        #pragma unroll
        for (int k = 0; k < 8; k++) {
            int idx = tid + k*256;
            int row = idx >> 4, q = idx & 15;
            CP_ASYNC16(uWb + (uint32_t)(row*LDT + q*8)*2,
                       w2h + (size_t)row*HID + r0 + q*8);
        }
        CP_COMMIT();
        if (tid < 128) bias1[tid] = eb1[(size_t)e*HID + r0 + tid];
        CP_WAIT1();                 // W1(rc) in Wa complete
        __syncthreads();            // visible to all; X gather also covered (rc=0)

        // ---- GEMM1: H = X @ W1(rc)^T
        float h[2][8][4];
        #pragma unroll
        for (int mt = 0; mt < 2; mt++)
            #pragma unroll
            for (int nt = 0; nt < 8; nt++)
                #pragma unroll
                for (int q = 0; q < 4; q++) h[mt][nt][q] = 0.f;

        #pragma unroll 2
        for (int ks2 = 0; ks2 < 8; ks2++) {
            const uint32_t kb = ks2 * 32;
            uint32_t ah[2][4];
            ldsm4(aXh + kb,             ah[0]);
            ldsm4(aXh + kb + 16*LDT*2,  ah[1]);
            #pragma unroll
            for (int ntp = 0; ntp < 4; ntp++) {
                uint32_t bh[4];
                ldsm4(bW1 + ntp*16*LDT*2 + kb, bh);
                #pragma unroll
                for (int mt = 0; mt < 2; mt++) {
                    mma16816(h[mt][ntp*2],   ah[mt], bh);
                    mma16816(h[mt][ntp*2+1], ah[mt], bh + 2);
                }
            }
        }

        // ---- gelu + bias -> Hh
        #pragma unroll
        for (int mt = 0; mt < 2; mt++) {
            #pragma unroll
            for (int nt = 0; nt < 8; nt++) {
                int gm = m0 + mt*16 + er;
                int gn = n0 + nt*8 + ec;
                float b1a = bias1[gn], b1b = bias1[gn+1];
                float u0 = h[mt][nt][0] + b1a;
                float u1 = h[mt][nt][1] + b1b;
                float u2 = h[mt][nt][2] + b1a;
                float u3 = h[mt][nt][3] + b1b;
                u0 = 0.5f*u0*(1.0f + erff(u0*0.70710678118654752f));
                u1 = 0.5f*u1*(1.0f + erff(u1*0.70710678118654752f));
                u2 = 0.5f*u2*(1.0f + erff(u2*0.70710678118654752f));
                u3 = 0.5f*u3*(1.0f + erff(u3*0.70710678118654752f));
                *reinterpret_cast<uint32_t*>(Hh + gm*LDT + gn)     = pack_bf2(u0, u1);
                *reinterpret_cast<uint32_t*>(Hh + (gm+8)*LDT + gn) = pack_bf2(u2, u3);
            }
        }
        __syncthreads();            // Hh ready; Wa reads (GEMM1) all done

        // issue W1(rc+1) -> Wa
        if (rc < 3) {
            #pragma unroll
            for (int k = 0; k < 8; k++) {
                int idx = tid + k*256;
                int row = idx >> 4, q = idx & 15;
                CP_ASYNC16(uWa + (uint32_t)(row*LDT + q*8)*2,
                           w1h + (size_t)(r0 + 128 + row)*C + q*8);
            }
            CP_COMMIT();
            CP_WAIT1();             // W2(rc) in Wb complete
        } else {
            CP_WAIT0();
        }
        __syncthreads();

        // ---- GEMM2: Y += H @ W2(rc)^T
        #pragma unroll 2
        for (int ks2 = 0; ks2 < 8; ks2++) {
            const uint32_t kb = ks2 * 32;
            uint32_t ah[2][4];
            ldsm4(aHh + kb,            ah[0]);
            ldsm4(aHh + kb + 16*LDT*2, ah[1]);
            #pragma unroll
            for (int ntp = 0; ntp < 4; ntp++) {
                uint32_t bh[4];
                ldsm4(bW2 + ntp*16*LDT*2 + kb, bh);
                #pragma unroll
                for (int mt = 0; mt < 2; mt++) {
                    mma16816(yacc[mt][ntp*2],   ah[mt], bh);
                    mma16816(yacc[mt][ntp*2+1], ah[mt], bh + 2);
                }
            }
        }
        __syncthreads();            // Wb reads done before next iteration's fill
    }

    // ---- epilogue
    #pragma unroll
    for (int mt = 0; mt < 2; mt++) {
        #pragma unroll
        for (int nt = 0; nt < 8; nt++) {
            int slot = m0 + mt*16 + er;
            int cc   = n0 + nt*8 + ec;
            float b2a = bias2[cc], b2b = bias2[cc+1];
            if (slot < rem) {
                float2 o = { yacc[mt][nt][0] + b2a, yacc[mt][nt][1] + b2b };
                *reinterpret_cast<float2*>(
                    g_ybuf + ((size_t)e*NPIX + tile0 + slot)*C + cc) = o;
            }
            if (slot + 8 < rem) {
                float2 o = { yacc[mt][nt][2] + b2a, yacc[mt][nt][3] + b2b };
                *reinterpret_cast<float2*>(
                    g_ybuf + ((size_t)e*NPIX + tile0 + slot + 8)*C + cc) = o;
            }
        }
    }
}

// ---------------- kernel G: weighted gather + residual ------------------
__global__ void k_gather(const float* __restrict__ x, float* __restrict__ out) {
    __shared__ float tile[C*33];
    const int t = threadIdx.x;
    const int lane = t & 31, w = t >> 5;
    const int pix0 = blockIdx.x * 32;
    const int b = pix0 >> 12;

    #pragma unroll
    for (int k = 0; k < 4; k++) {
        int px  = w*4 + k;
        int pix = pix0 + px;
        float a0 = 0.f, a1 = 0.f, a2 = 0.f, a3 = 0.f;
        #pragma unroll
        for (int e = 0; e < E; e++) {
            float wv = g_route[(size_t)e*NPIX + pix];
            if (wv > 0.f) {
                int sl = g_slot[e*NPIX + pix];
                const float* row = g_ybuf + ((size_t)e*NPIX + sl)*C;
                a0 += wv * row[lane];
                a1 += wv * row[lane + 32];
                a2 += wv * row[lane + 64];
                a3 += wv * row[lane + 96];
            }
        }
        tile[(lane)*33 + px]      = a0;
        tile[(lane+32)*33 + px]   = a1;
        tile[(lane+64)*33 + px]   = a2;
        tile[(lane+96)*33 + px]   = a3;
    }
    __syncthreads();
    const size_t base = (size_t)b*(C-1)*HW + pix0;
    for (int idx = t; idx < C*32; idx += 256) {
        int c = idx >> 5, px = idx & 31;
        size_t a = base + (size_t)c*HW + px;
        out[a] = x[a] + tile[c*33 + px];
    }
}

// ---------------- kernel D: aux scalar -----------------------------------
__global__ void k_aux(const float* __restrict__ proto, float* __restrict__ out, int out_size) {
    __shared__ float pn[E][P];
    __shared__ float red[128];
    int t = threadIdx.x;
    if (t < E) {
        float s = 0.f;
        for (int p = 0; p < P; p++) { float v = proto[t*P + p]; s += v*v; }
        float inv = 1.0f / sqrtf(s);
        for (int p = 0; p < P; p++) pn[t][p] = proto[t*P + p] * inv;
    }
    __syncthreads();
    float s = 0.f;
    for (int idx = t; idx < E*E; idx += 128) {
        int i = idx / E, j = idx % E;
        float d = 0.f;
        for (int p = 0; p < P; p++) d += pn[i][p] * pn[j][p];
        d -= (i == j) ? 1.0f : 0.0f;
        s += d*d;
    }
    red[t] = s;
    __syncthreads();
    for (int st = 64; st; st >>= 1) { if (t < st) red[t] += red[t + st]; __syncthreads(); }
    if (t == 0) {
        float ortho = sqrtf(red[0]);
        float aux = 0.f;
        for (int e = 0; e < E; e++)
            aux += (g_probsum[e] * (1.0f/NPIX)) * (g_loadsum[e] * (1.0f/NPIX));
        aux *= (float)E;
        if (out_size > BB*C*HW) out[BB*C*HW] = aux + 0.5f * ortho;
    }
}

// ---------------- launcher ------------------------------------------------
extern "C" void kernel_launch(void* const* d_in, const int* in_sizes, int n_in,
                              void* d_out, int out_size) {
    const float* x      = (const float*)d_in[0];
    const float* proto  = (const float*)d_in[1];
    const float* ctx_w  = (const float*)d_in[2];
    const float* ctx_b  = (const float*)d_in[3];
    const float* inp_w  = (const float*)d_in[4];
    const float* inp_b  = (const float*)d_in[5];
    const float* wq     = (const float*)d_in[6];
    const float* bq     = (const float*)d_in[7];
    const float* wk     = (const float*)d_in[8];
    const float* bk     = (const float*)d_in[9];
    const float* wv     = (const float*)d_in[10];
    const float* bv     = (const float*)d_in[11];
    const float* wo     = (const float*)d_in[12];
    const float* bo     = (const float*)d_in[13];
    const float* ln_g   = (const float*)d_in[14];
    const float* ln_b   = (const float*)d_in[15];
    const float* ew1    = (const float*)d_in[16];
    const float* eb1    = (const float*)d_in[17];
    const float* ew2    = (const float*)d_in[18];
    const float* eb2    = (const float*)d_in[19];
    float* out = (float*)d_out;

    const int smem_mlp  = 4 * 128 * LDT * (int)sizeof(__nv_bfloat16);  // 139264 B
    const int smem_attn = (4*P*P + 2*P*C) * (int)sizeof(float);        // 131072 B
    cudaFuncSetAttribute(k_mlp,  cudaFuncAttributeMaxDynamicSharedMemorySize, smem_mlp);
    cudaFuncSetAttribute(k_attn, cudaFuncAttributeMaxDynamicSharedMemorySize, smem_attn);

    k_cvt<<<(E*HID*C + 255)/256, 256>>>(ew1, ew2);
    k_gc<<<BB*C, 128>>>(x);
    k_attn<<<BB, 256, smem_attn>>>(proto, ctx_w, ctx_b, inp_w, inp_b,
                                   wq, bq, wk, bk, wv, bv, wo, bo, ln_g, ln_b);
    k_route<<<NPIX/64, 256>>>(x);
    k_mlp<<<dim3(NPIX/128, E), 256, smem_mlp>>>(x, eb1, eb2);
    k_gather<<<NPIX/32, 256>>>(x, out);
    k_aux<<<1, 128>>>(proto, out, out_size);
}

// round 15
// speedup vs baseline: 1.3220x; 1.0839x over previous
#include <cuda_runtime.h>
#include <cuda_bf16.h>
#include <math.h>
#include <stdint.h>

#define E    11
#define KSEL 6
#define P    64
#define NH   4
#define HD   16
#define SEQ  12
#define BB   8
#define C    128
#define HH   64
#define WW   64
#define HW   (HH*WW)        /* 4096  */
#define NPIX (BB*HW)        /* 32768 */
#define HID  512
#define LDT  136            /* smem tile row stride in bf16 (272B = 17*16B, conflict-free) */

// ---------------- device scratch (no allocation allowed) ----------------
__device__ float g_gc[BB*C];
__device__ float g_Wr[BB*E*C];
__device__ float g_br[BB*E];
__device__ float g_route[E*NPIX];
__device__ float g_probsum[E];
__device__ float g_loadsum[E];
__device__ int   g_cnt[E];
__device__ int   g_pidx[E*NPIX];   // [e][slot] -> pixel
__device__ __align__(16) __nv_bfloat16 g_w1h[E*HID*C];  // [e][r][c]
__device__ __align__(16) __nv_bfloat16 g_w2h[E*C*HID];  // [e][c][j]

// ---------------- mma/ldmatrix helpers (sm_80-era, no 'a' gating) --------
__device__ __forceinline__ uint32_t smem_u32(const void* p) {
    uint32_t a;
    asm("{ .reg .u64 t; cvta.to.shared.u64 t, %1; cvt.u32.u64 %0, t; }"
        : "=r"(a) : "l"(p));
    return a;
}
__device__ __forceinline__ void ldsm4(uint32_t a, uint32_t* r) {
    asm volatile("ldmatrix.sync.aligned.m8n8.x4.shared.b16 {%0,%1,%2,%3}, [%4];"
        : "=r"(r[0]), "=r"(r[1]), "=r"(r[2]), "=r"(r[3]) : "r"(a));
}
__device__ __forceinline__ void mma16816(float* c, const uint32_t* a, const uint32_t* b) {
    asm volatile("mma.sync.aligned.m16n8k16.row.col.f32.bf16.bf16.f32 "
        "{%0,%1,%2,%3}, {%4,%5,%6,%7}, {%8,%9}, {%0,%1,%2,%3};"
        : "+f"(c[0]), "+f"(c[1]), "+f"(c[2]), "+f"(c[3])
        : "r"(a[0]), "r"(a[1]), "r"(a[2]), "r"(a[3]), "r"(b[0]), "r"(b[1]));
}
__device__ __forceinline__ uint32_t pack_bf2(float x, float y) {
    __nv_bfloat162 v = __floats2bfloat162_rn(x, y);
    return *reinterpret_cast<uint32_t*>(&v);
}
#define CP_ASYNC16(dst, src) \
    asm volatile("cp.async.cg.shared.global [%0], [%1], 16;" :: "r"(dst), "l"(src))
#define CP_COMMIT() asm volatile("cp.async.commit_group;" ::: "memory")
#define CP_WAIT1()  asm volatile("cp.async.wait_group 1;" ::: "memory")
#define CP_WAIT0()  asm volatile("cp.async.wait_group 0;" ::: "memory")

// ---------------- prep: convert weights to bf16 ---------------------------
__global__ void k_cvt(const float* __restrict__ ew1, const float* __restrict__ ew2) {
    int i = blockIdx.x * 256 + threadIdx.x;
    if (i < E*HID*C) {
        g_w1h[i] = __float2bfloat16(ew1[i]);
        g_w2h[i] = __float2bfloat16(ew2[i]);
    }
}

// ---------------- kernel 0: gc means + out=x + zero counters ------------
__global__ void k_gc(const float* __restrict__ x, float* __restrict__ out) {
    int bc = blockIdx.x;
    const float4* src = reinterpret_cast<const float4*>(x + (size_t)bc * HW);
    float4* dst = reinterpret_cast<float4*>(out + (size_t)bc * HW);
    float s = 0.f;
    for (int i = threadIdx.x; i < HW/4; i += 128) {
        float4 v = src[i];
        dst[i] = v;                                // residual init: out = x
        s += v.x + v.y + v.z + v.w;
    }
    __shared__ float red[4];
    for (int o = 16; o; o >>= 1) s += __shfl_down_sync(0xffffffffu, s, o);
    if ((threadIdx.x & 31) == 0) red[threadIdx.x >> 5] = s;
    __syncthreads();
    if (threadIdx.x == 0) {
        float t = red[0] + red[1] + red[2] + red[3];
        g_gc[bc] = t * (1.0f / HW);
    }
    if (bc == 0 && threadIdx.x < E) {
        g_probsum[threadIdx.x] = 0.f;
        g_loadsum[threadIdx.x] = 0.f;
        g_cnt[threadIdx.x] = 0;
    }
}

// ---------------- kernel A: attention path + router weight folding ------
__global__ void k_attn(const float* __restrict__ proto,
                       const float* __restrict__ ctx_w, const float* __restrict__ ctx_b,
                       const float* __restrict__ inp_w, const float* __restrict__ inp_b,
                       const float* __restrict__ wq, const float* __restrict__ bq,
                       const float* __restrict__ wk, const float* __restrict__ bk,
                       const float* __restrict__ wv, const float* __restrict__ bv,
                       const float* __restrict__ wo, const float* __restrict__ bo,
                       const float* __restrict__ ln_g, const float* __restrict__ ln_b) {
    extern __shared__ float wsm[];
    float* swq  = wsm;               // P*P = 4096
    float* swk  = swq + P*P;
    float* swv  = swk + P*P;
    float* swo  = swv + P*P;
    float* sctx = swo + P*P;         // P*C = 8192
    float* sinp = sctx + P*C;        // P*C = 8192

    int b = blockIdx.x;
    int t = threadIdx.x;                       // 256 threads
    __shared__ float seq[SEQ][P], qs[SEQ][P], ks[SEQ][P], vs[SEQ][P], ao[SEQ][P], o2[SEQ][P];
    __shared__ float gx[C];
    __shared__ float mstat[SEQ], istat[SEQ];

    {
        const float4* s4;
        float4* d4;
        s4 = reinterpret_cast<const float4*>(wq);  d4 = reinterpret_cast<float4*>(swq);
        for (int i = t; i < P*P/4; i += 256) d4[i] = s4[i];
        s4 = reinterpret_cast<const float4*>(wk);  d4 = reinterpret_cast<float4*>(swk);
        for (int i = t; i < P*P/4; i += 256) d4[i] = s4[i];
        s4 = reinterpret_cast<const float4*>(wv);  d4 = reinterpret_cast<float4*>(swv);
        for (int i = t; i < P*P/4; i += 256) d4[i] = s4[i];
        s4 = reinterpret_cast<const float4*>(wo);  d4 = reinterpret_cast<float4*>(swo);
        for (int i = t; i < P*P/4; i += 256) d4[i] = s4[i];
        s4 = reinterpret_cast<const float4*>(ctx_w); d4 = reinterpret_cast<float4*>(sctx);
        for (int i = t; i < P*C/4; i += 256) d4[i] = s4[i];
        s4 = reinterpret_cast<const float4*>(inp_w); d4 = reinterpret_cast<float4*>(sinp);
        for (int i = t; i < P*C/4; i += 256) d4[i] = s4[i];
    }
    if (t < C) gx[t] = g_gc[b*C + t];
    __syncthreads();

    if (t < P) {
        float a = ctx_b[t];
        for (int c = 0; c < C; c++) a += gx[c] * sctx[t*C + c];
        seq[0][t] = a;
    }
    for (int z = t; z < E*P; z += 256) seq[1 + z/P][z%P] = proto[z];
    __syncthreads();

    for (int z = t; z < SEQ*P; z += 256) {
        int s = z >> 6, p = z & 63;
        float aq = bq[p], ak = bk[p], av = bv[p];
        for (int q = 0; q < P; q++) {
            float sv = seq[s][q];
            aq += sv * swq[p*P + q];
            ak += sv * swk[p*P + q];
            av += sv * swv[p*P + q];
        }
        qs[s][p] = aq; ks[s][p] = ak; vs[s][p] = av;
    }
    __syncthreads();

    if (t < NH*SEQ) {
        int n = t / SEQ, i = t % SEQ;
        float sc[SEQ];
        float mx = -1e30f;
        for (int j = 0; j < SEQ; j++) {
            float a = 0.f;
            for (int d = 0; d < HD; d++) a += qs[i][n*HD + d] * ks[j][n*HD + d];
            a *= 0.25f;
            sc[j] = a; mx = fmaxf(mx, a);
        }
        float sm = 0.f;
        for (int j = 0; j < SEQ; j++) { sc[j] = expf(sc[j] - mx); sm += sc[j]; }
        float inv = 1.0f / sm;
        for (int d = 0; d < HD; d++) {
            float a = 0.f;
            for (int j = 0; j < SEQ; j++) a += sc[j] * vs[j][n*HD + d];
            ao[i][n*HD + d] = a * inv;
        }
    }
    __syncthreads();

    for (int z = t; z < SEQ*P; z += 256) {
        int s = z >> 6, p = z & 63;
        float a = bo[p];
        for (int q = 0; q < P; q++) a += ao[s][q] * swo[p*P + q];
        o2[s][p] = a + seq[s][p];
    }
    __syncthreads();

    if (t < SEQ) {
        float m = 0.f;
        for (int p = 0; p < P; p++) m += o2[t][p];
        m *= (1.0f / P);
        float v = 0.f;
        for (int p = 0; p < P; p++) { float d = o2[t][p] - m; v += d*d; }
        v *= (1.0f / P);
        mstat[t] = m; istat[t] = 1.0f / sqrtf(v + 1e-5f);
    }
    __syncthreads();

    for (int z = t; z < E*P; z += 256) {
        int s = z / P + 1, p = z % P;
        seq[s][p] = (o2[s][p] - mstat[s]) * istat[s] * ln_g[p] + ln_b[p];
    }
    __syncthreads();

    for (int z = t; z < E*C; z += 256) {
        int e = z / C, c = z % C;
        float a = 0.f;
        for (int p = 0; p < P; p++) a += seq[e+1][p] * sinp[p*C + c];
        g_Wr[(b*E + e)*C + c] = a;
    }
    if (t < E) {
        float a = 0.f;
        for (int p = 0; p < P; p++) a += seq[t+1][p] * inp_b[p];
        g_br[b*E + t] = a;
    }
}

// ---------------- kernel B: routing + per-expert compaction -------------
// 512 blocks x 256 threads; 64 pixels/block; 4 threads per pixel (c-slices).
__global__ void k_route(const float* __restrict__ x) {
    const int t = threadIdx.x;
    const int p = t & 63;
    const int j = t >> 6;
    const int pix0 = blockIdx.x * 64;
    const int b = pix0 / HW;
    const int pix = pix0 + p;

    __shared__ float wr[E*C];
    __shared__ float br[E];
    __shared__ float part[4][64*13];
    __shared__ float psum[E];
    __shared__ int   scnt[E], sbase[E];

    for (int i = t; i < E*C; i += 256) wr[i] = g_Wr[b*E*C + i];
    if (t < E) {
        br[t] = g_br[b*E + t];
        psum[t] = 0.f;
        scnt[t] = 0;
    }
    __syncthreads();

    {
        float pr[E];
        #pragma unroll
        for (int e = 0; e < E; e++) pr[e] = 0.f;
        const float* xp = x + (size_t)b*C*HW + (pix - b*HW);
        for (int ci = 0; ci < 32; ci++) {
            int c = j*32 + ci;
            float xv = xp[(size_t)c * HW];
            #pragma unroll
            for (int e = 0; e < E; e++) pr[e] += xv * wr[e*C + c];
        }
        #pragma unroll
        for (int e = 0; e < E; e++) part[j][p*13 + e] = pr[e];
    }
    __syncthreads();

    int loc[E];
    if (t < 64) {
        float pr[E];
        #pragma unroll
        for (int e = 0; e < E; e++)
            pr[e] = br[e] + part[0][t*13 + e] + part[1][t*13 + e]
                          + part[2][t*13 + e] + part[3][t*13 + e];

        float mx = -1e30f;
        #pragma unroll
        for (int e = 0; e < E; e++) { pr[e] *= 0.125f; mx = fmaxf(mx, pr[e]); }
        float sm = 0.f;
        #pragma unroll
        for (int e = 0; e < E; e++) { pr[e] = expf(pr[e] - mx); sm += pr[e]; }
        float invs = 1.0f / sm;
        #pragma unroll
        for (int e = 0; e < E; e++) pr[e] *= invs;

        int used = 0;
        float tsum = 0.f;
        #pragma unroll
        for (int k2 = 0; k2 < KSEL; k2++) {
            float bv = -1.f; int bi = 0;
            #pragma unroll
            for (int e = 0; e < E; e++)
                if (!((used >> e) & 1) && pr[e] > bv) { bv = pr[e]; bi = e; }
            used |= 1 << bi;
            tsum += bv;
        }
        float invt = 1.0f / tsum;

        #pragma unroll
        for (int e = 0; e < E; e++) {
            int selq = (used >> e) & 1;
            g_route[(size_t)e * NPIX + pix] = selq ? pr[e] * invt : 0.f;
            atomicAdd(&psum[e], pr[e]);
            loc[e] = selq ? atomicAdd(&scnt[e], 1) : -1;
        }
    }
    __syncthreads();
    if (t < E) {
        sbase[t] = atomicAdd(&g_cnt[t], scnt[t]);
        atomicAdd(&g_probsum[t], psum[t]);
        atomicAdd(&g_loadsum[t], (float)scnt[t]);
    }
    __syncthreads();
    if (t < 64) {
        #pragma unroll
        for (int e = 0; e < E; e++) {
            if (loc[e] >= 0) {
                int slot = sbase[e] + loc[e];
                g_pidx[e*NPIX + slot] = pix;
            }
        }
    }
}

// ---------------- kernel C: HMMA grouped-GEMM expert MLPs ----------------
// Double-buffered cp.async weight pipeline; fused epilogue: atomicAdd of
// wv*(y+b2) directly into out (out pre-initialized to x by k_gc).
__global__ void __launch_bounds__(256, 1)
k_mlp(const float* __restrict__ x,
      const float* __restrict__ eb1,
      const float* __restrict__ eb2,
      float* __restrict__ out) {
    extern __shared__ __align__(16) __nv_bfloat16 sm[];
    __nv_bfloat16* Xh = sm;                  // [128][LDT]
    __nv_bfloat16* Wa = Xh + 128*LDT;        // W1 chunk
    __nv_bfloat16* Wb = Wa + 128*LDT;        // W2 chunk
    __nv_bfloat16* Hh = Wb + 128*LDT;
    __shared__ int   pid[128];
    __shared__ float wt[128];
    __shared__ float bias1[128], bias2[128];

    const int e     = blockIdx.y;
    const int cnt   = g_cnt[e];
    const int tile0 = blockIdx.x * 128;
    if (tile0 >= cnt) return;
    const int rem = min(128, cnt - tile0);
    const int tid = threadIdx.x;
    const int wid = tid >> 5, lane = tid & 31;

    const __nv_bfloat16* w1h = g_w1h + (size_t)e*HID*C;
    const __nv_bfloat16* w2h = g_w2h + (size_t)e*C*HID;

    const uint32_t uXh = smem_u32(Xh);
    const uint32_t uWa = smem_u32(Wa);
    const uint32_t uWb = smem_u32(Wb);
    const uint32_t uHh = smem_u32(Hh);

    // prologue: prefetch W1 chunk 0 into Wa
    #pragma unroll
    for (int k = 0; k < 8; k++) {
        int idx = tid + k*256;
        int row = idx >> 4, q = idx & 15;
        CP_ASYNC16(uWa + (uint32_t)(row*LDT + q*8)*2,
                   w1h + (size_t)row*C + q*8);
    }
    CP_COMMIT();

    if (tid < 128) {
        int p = g_pidx[e*NPIX + tile0 + min(tid, rem - 1)];
        pid[tid]   = p;
        wt[tid]    = g_route[(size_t)e*NPIX + p];
        bias2[tid] = eb2[(size_t)e*C + tid];
    }
    __syncthreads();

    // gather X -> bf16 [slot][c]  (overlaps with W1(0) prefetch)
    for (int idx = tid; idx < 128*128; idx += 256) {
        int slot = idx & 127, c = idx >> 7;
        int p = pid[slot];
        int b = p >> 12;
        float v = x[(size_t)b*(C-1)*HW + (size_t)c*HW + p];
        Xh[slot*LDT + c] = __float2bfloat16(v);
    }

    const int m0 = (wid >> 1) * 32;
    const int n0 = (wid & 1) * 64;
    const int lr = lane & 7, lq = lane >> 3;
    const int aoff = ((lr + (lq & 1)*8) * LDT + (lq >> 1)*8) * 2;
    const int boff = ((lr + (lq >> 1)*8) * LDT + (lq & 1)*8) * 2;
    const int er = lane >> 2;
    const int ec = (lane & 3) * 2;

    const uint32_t aXh = uXh + m0*LDT*2 + aoff;
    const uint32_t aHh = uHh + m0*LDT*2 + aoff;
    const uint32_t bW1 = uWa + n0*LDT*2 + boff;
    const uint32_t bW2 = uWb + n0*LDT*2 + boff;

    float yacc[2][8][4];
    #pragma unroll
    for (int mt = 0; mt < 2; mt++)
        #pragma unroll
        for (int nt = 0; nt < 8; nt++)
            #pragma unroll
            for (int q = 0; q < 4; q++) yacc[mt][nt][q] = 0.f;

    for (int rc = 0; rc < 4; rc++) {
        const int r0 = rc * 128;

        // issue W2(rc) -> Wb
        #pragma unroll
        for (int k = 0; k < 8; k++) {
            int idx = tid + k*256;
            int row = idx >> 4, q = idx & 15;
            CP_ASYNC16(uWb + (uint32_t)(row*LDT + q*8)*2,
                       w2h + (size_t)row*HID + r0 + q*8);
        }
        CP_COMMIT();
        if (tid < 128) bias1[tid] = eb1[(size_t)e*HID + r0 + tid];
        CP_WAIT1();                 // W1(rc) complete
        __syncthreads();

        // ---- GEMM1: H = X @ W1(rc)^T
        float h[2][8][4];
        #pragma unroll
        for (int mt = 0; mt < 2; mt++)
            #pragma unroll
            for (int nt = 0; nt < 8; nt++)
                #pragma unroll
                for (int q = 0; q < 4; q++) h[mt][nt][q] = 0.f;

        #pragma unroll 2
        for (int ks2 = 0; ks2 < 8; ks2++) {
            const uint32_t kb = ks2 * 32;
            uint32_t ah[2][4];
            ldsm4(aXh + kb,             ah[0]);
            ldsm4(aXh + kb + 16*LDT*2,  ah[1]);
            #pragma unroll
            for (int ntp = 0; ntp < 4; ntp++) {
                uint32_t bh[4];
                ldsm4(bW1 + ntp*16*LDT*2 + kb, bh);
                #pragma unroll
                for (int mt = 0; mt < 2; mt++) {
                    mma16816(h[mt][ntp*2],   ah[mt], bh);
                    mma16816(h[mt][ntp*2+1], ah[mt], bh + 2);
                }
            }
        }

        // ---- gelu + bias -> Hh
        #pragma unroll
        for (int mt = 0; mt < 2; mt++) {
            #pragma unroll
            for (int nt = 0; nt < 8; nt++) {
                int gm = m0 + mt*16 + er;
                int gn = n0 + nt*8 + ec;
                float b1a = bias1[gn], b1b = bias1[gn+1];
                float u0 = h[mt][nt][0] + b1a;
                float u1 = h[mt][nt][1] + b1b;
                float u2 = h[mt][nt][2] + b1a;
                float u3 = h[mt][nt][3] + b1b;
                u0 = 0.5f*u0*(1.0f + erff(u0*0.70710678118654752f));
                u1 = 0.5f*u1*(1.0f + erff(u1*0.70710678118654752f));
                u2 = 0.5f*u2*(1.0f + erff(u2*0.70710678118654752f));
                u3 = 0.5f*u3*(1.0f + erff(u3*0.70710678118654752f));
                *reinterpret_cast<uint32_t*>(Hh + gm*LDT + gn)     = pack_bf2(u0, u1);
                *reinterpret_cast<uint32_t*>(Hh + (gm+8)*LDT + gn) = pack_bf2(u2, u3);
            }
        }
        __syncthreads();            // Hh ready; Wa reads done

        // issue W1(rc+1) -> Wa
        if (rc < 3) {
            #pragma unroll
            for (int k = 0; k < 8; k++) {
                int idx = tid + k*256;
                int row = idx >> 4, q = idx & 15;
                CP_ASYNC16(uWa + (uint32_t)(row*LDT + q*8)*2,
                           w1h + (size_t)(r0 + 128 + row)*C + q*8);
            }
            CP_COMMIT();
            CP_WAIT1();             // W2(rc) complete
        } else {
            CP_WAIT0();
        }
        __syncthreads();

        // ---- GEMM2: Y += H @ W2(rc)^T
        #pragma unroll 2
        for (int ks2 = 0; ks2 < 8; ks2++) {
            const uint32_t kb = ks2 * 32;
            uint32_t ah[2][4];
            ldsm4(aHh + kb,            ah[0]);
            ldsm4(aHh + kb + 16*LDT*2, ah[1]);
            #pragma unroll
            for (int ntp = 0; ntp < 4; ntp++) {
                uint32_t bh[4];
                ldsm4(bW2 + ntp*16*LDT*2 + kb, bh);
                #pragma unroll
                for (int mt = 0; mt < 2; mt++) {
                    mma16816(yacc[mt][ntp*2],   ah[mt], bh);
                    mma16816(yacc[mt][ntp*2+1], ah[mt], bh + 2);
                }
            }
        }
        __syncthreads();            // Wb reads done before next fill
    }

    // ---- fused epilogue: out += wv * (y + b2), scattered atomics
    #pragma unroll
    for (int mt = 0; mt < 2; mt++) {
        #pragma unroll
        for (int nt = 0; nt < 8; nt++) {
            int slot = m0 + mt*16 + er;
            int cc   = n0 + nt*8 + ec;
            float b2a = bias2[cc], b2b = bias2[cc+1];
            if (slot < rem) {
                int p = pid[slot];
                int b = p >> 12;
                float w = wt[slot];
                float* dst = out + (size_t)b*(C-1)*HW + (size_t)cc*HW + p;
                atomicAdd(dst,      w * (yacc[mt][nt][0] + b2a));
                atomicAdd(dst + HW, w * (yacc[mt][nt][1] + b2b));
            }
            if (slot + 8 < rem) {
                int p = pid[slot + 8];
                int b = p >> 12;
                float w = wt[slot + 8];
                float* dst = out + (size_t)b*(C-1)*HW + (size_t)cc*HW + p;
                atomicAdd(dst,      w * (yacc[mt][nt][2] + b2a));
                atomicAdd(dst + HW, w * (yacc[mt][nt][3] + b2b));
            }
        }
    }
}

// ---------------- kernel D: aux scalar -----------------------------------
__global__ void k_aux(const float* __restrict__ proto, float* __restrict__ out, int out_size) {
    __shared__ float pn[E][P];
    __shared__ float red[128];
    int t = threadIdx.x;
    if (t < E) {
        float s = 0.f;
        for (int p = 0; p < P; p++) { float v = proto[t*P + p]; s += v*v; }
        float inv = 1.0f / sqrtf(s);
        for (int p = 0; p < P; p++) pn[t][p] = proto[t*P + p] * inv;
    }
    __syncthreads();
    float s = 0.f;
    for (int idx = t; idx < E*E; idx += 128) {
        int i = idx / E, j = idx % E;
        float d = 0.f;
        for (int p = 0; p < P; p++) d += pn[i][p] * pn[j][p];
        d -= (i == j) ? 1.0f : 0.0f;
        s += d*d;
    }
    red[t] = s;
    __syncthreads();
    for (int st = 64; st; st >>= 1) { if (t < st) red[t] += red[t + st]; __syncthreads(); }
    if (t == 0) {
        float ortho = sqrtf(red[0]);
        float aux = 0.f;
        for (int e = 0; e < E; e++)
            aux += (g_probsum[e] * (1.0f/NPIX)) * (g_loadsum[e] * (1.0f/NPIX));
        aux *= (float)E;
        if (out_size > BB*C*HW) out[BB*C*HW] = aux + 0.5f * ortho;
    }
}

// ---------------- launcher ------------------------------------------------
extern "C" void kernel_launch(void* const* d_in, const int* in_sizes, int n_in,
                              void* d_out, int out_size) {
    const float* x      = (const float*)d_in[0];
    const float* proto  = (const float*)d_in[1];
    const float* ctx_w  = (const float*)d_in[2];
    const float* ctx_b  = (const float*)d_in[3];
    const float* inp_w  = (const float*)d_in[4];
    const float* inp_b  = (const float*)d_in[5];
    const float* wq     = (const float*)d_in[6];
    const float* bq     = (const float*)d_in[7];
    const float* wk     = (const float*)d_in[8];
    const float* bk     = (const float*)d_in[9];
    const float* wv     = (const float*)d_in[10];
    const float* bv     = (const float*)d_in[11];
    const float* wo     = (const float*)d_in[12];
    const float* bo     = (const float*)d_in[13];
    const float* ln_g   = (const float*)d_in[14];
    const float* ln_b   = (const float*)d_in[15];
    const float* ew1    = (const float*)d_in[16];
    const float* eb1    = (const float*)d_in[17];
    const float* ew2    = (const float*)d_in[18];
    const float* eb2    = (const float*)d_in[19];
    float* out = (float*)d_out;

    const int smem_mlp  = 4 * 128 * LDT * (int)sizeof(__nv_bfloat16);  // 139264 B
    const int smem_attn = (4*P*P + 2*P*C) * (int)sizeof(float);        // 131072 B
    cudaFuncSetAttribute(k_mlp,  cudaFuncAttributeMaxDynamicSharedMemorySize, smem_mlp);
    cudaFuncSetAttribute(k_attn, cudaFuncAttributeMaxDynamicSharedMemorySize, smem_attn);

    k_cvt<<<(E*HID*C + 255)/256, 256>>>(ew1, ew2);
    k_gc<<<BB*C, 128>>>(x, out);
    k_attn<<<BB, 256, smem_attn>>>(proto, ctx_w, ctx_b, inp_w, inp_b,
                                   wq, bq, wk, bk, wv, bv, wo, bo, ln_g, ln_b);
    k_route<<<NPIX/64, 256>>>(x);
    k_mlp<<<dim3(NPIX/128, E), 256, smem_mlp>>>(x, eb1, eb2, out);
    k_aux<<<1, 128>>>(proto, out, out_size);
}

// round 16
// speedup vs baseline: 1.4647x; 1.1079x over previous
#include <cuda_runtime.h>
#include <cuda_bf16.h>
#include <math.h>
#include <stdint.h>

#define E    11
#define KSEL 6
#define P    64
#define NH   4
#define HD   16
#define SEQ  12
#define BB   8
#define C    128
#define HH   64
#define WW   64
#define HW   (HH*WW)        /* 4096  */
#define NPIX (BB*HW)        /* 32768 */
#define HID  512
#define LDT  136            /* smem tile row stride in bf16 (272B = 17*16B, conflict-free) */

// ---------------- device scratch (no allocation allowed) ----------------
__device__ float g_gc[BB*C];
__device__ float g_Wr[BB*E*C];
__device__ float g_br[BB*E];
__device__ float g_route[E*NPIX];
__device__ float g_probsum[E];
__device__ float g_loadsum[E];
__device__ int   g_cnt[E];
__device__ int   g_pidx[E*NPIX];   // [e][slot] -> pixel
__device__ __align__(16) __nv_bfloat16 g_w1h[E*HID*C];  // [e][r][c]
__device__ __align__(16) __nv_bfloat16 g_w2h[E*C*HID];  // [e][c][j]

// ---------------- mma/ldmatrix helpers (sm_80-era, no 'a' gating) --------
__device__ __forceinline__ uint32_t smem_u32(const void* p) {
    uint32_t a;
    asm("{ .reg .u64 t; cvta.to.shared.u64 t, %1; cvt.u32.u64 %0, t; }"
        : "=r"(a) : "l"(p));
    return a;
}
__device__ __forceinline__ void ldsm4(uint32_t a, uint32_t* r) {
    asm volatile("ldmatrix.sync.aligned.m8n8.x4.shared.b16 {%0,%1,%2,%3}, [%4];"
        : "=r"(r[0]), "=r"(r[1]), "=r"(r[2]), "=r"(r[3]) : "r"(a));
}
__device__ __forceinline__ void mma16816(float* c, const uint32_t* a, const uint32_t* b) {
    asm volatile("mma.sync.aligned.m16n8k16.row.col.f32.bf16.bf16.f32 "
        "{%0,%1,%2,%3}, {%4,%5,%6,%7}, {%8,%9}, {%0,%1,%2,%3};"
        : "+f"(c[0]), "+f"(c[1]), "+f"(c[2]), "+f"(c[3])
        : "r"(a[0]), "r"(a[1]), "r"(a[2]), "r"(a[3]), "r"(b[0]), "r"(b[1]));
}
__device__ __forceinline__ uint32_t pack_bf2(float x, float y) {
    __nv_bfloat162 v = __floats2bfloat162_rn(x, y);
    return *reinterpret_cast<uint32_t*>(&v);
}
// fast gelu: u / (1 + exp(-(1.5957691*u + 0.0713548*u^3)))
__device__ __forceinline__ float fast_gelu(float u) {
    float z = u * fmaf(u*u, 0.0713548162726f, 1.5957691216057f);
    return __fdividef(u, 1.0f + __expf(-z));
}
#define CP_ASYNC16(dst, src) \
    asm volatile("cp.async.cg.shared.global [%0], [%1], 16;" :: "r"(dst), "l"(src))
#define CP_COMMIT() asm volatile("cp.async.commit_group;" ::: "memory")
#define CP_WAIT1()  asm volatile("cp.async.wait_group 1;" ::: "memory")
#define CP_WAIT0()  asm volatile("cp.async.wait_group 0;" ::: "memory")

// ---------------- prep: convert weights to bf16 ---------------------------
__global__ void k_cvt(const float* __restrict__ ew1, const float* __restrict__ ew2) {
    int i = blockIdx.x * 256 + threadIdx.x;
    if (i < E*HID*C) {
        g_w1h[i] = __float2bfloat16(ew1[i]);
        g_w2h[i] = __float2bfloat16(ew2[i]);
    }
}

// ---------------- kernel 0: gc means + out=x + zero counters ------------
__global__ void k_gc(const float* __restrict__ x, float* __restrict__ out) {
    int bc = blockIdx.x;
    const float4* src = reinterpret_cast<const float4*>(x + (size_t)bc * HW);
    float4* dst = reinterpret_cast<float4*>(out + (size_t)bc * HW);
    float s = 0.f;
    for (int i = threadIdx.x; i < HW/4; i += 128) {
        float4 v = src[i];
        dst[i] = v;                                // residual init: out = x
        s += v.x + v.y + v.z + v.w;
    }
    __shared__ float red[4];
    for (int o = 16; o; o >>= 1) s += __shfl_down_sync(0xffffffffu, s, o);
    if ((threadIdx.x & 31) == 0) red[threadIdx.x >> 5] = s;
    __syncthreads();
    if (threadIdx.x == 0) {
        float t = red[0] + red[1] + red[2] + red[3];
        g_gc[bc] = t * (1.0f / HW);
    }
    if (bc == 0 && threadIdx.x < E) {
        g_probsum[threadIdx.x] = 0.f;
        g_loadsum[threadIdx.x] = 0.f;
        g_cnt[threadIdx.x] = 0;
    }
}

// ---------------- kernel A: attention path + router weight folding ------
__global__ void k_attn(const float* __restrict__ proto,
                       const float* __restrict__ ctx_w, const float* __restrict__ ctx_b,
                       const float* __restrict__ inp_w, const float* __restrict__ inp_b,
                       const float* __restrict__ wq, const float* __restrict__ bq,
                       const float* __restrict__ wk, const float* __restrict__ bk,
                       const float* __restrict__ wv, const float* __restrict__ bv,
                       const float* __restrict__ wo, const float* __restrict__ bo,
                       const float* __restrict__ ln_g, const float* __restrict__ ln_b) {
    extern __shared__ float wsm[];
    float* swq  = wsm;               // P*P = 4096
    float* swk  = swq + P*P;
    float* swv  = swk + P*P;
    float* swo  = swv + P*P;
    float* sctx = swo + P*P;         // P*C = 8192
    float* sinp = sctx + P*C;        // P*C = 8192

    int b = blockIdx.x;
    int t = threadIdx.x;                       // 256 threads
    __shared__ float seq[SEQ][P], qs[SEQ][P], ks[SEQ][P], vs[SEQ][P], ao[SEQ][P], o2[SEQ][P];
    __shared__ float gx[C];
    __shared__ float mstat[SEQ], istat[SEQ];

    {
        const float4* s4;
        float4* d4;
        s4 = reinterpret_cast<const float4*>(wq);  d4 = reinterpret_cast<float4*>(swq);
        for (int i = t; i < P*P/4; i += 256) d4[i] = s4[i];
        s4 = reinterpret_cast<const float4*>(wk);  d4 = reinterpret_cast<float4*>(swk);
        for (int i = t; i < P*P/4; i += 256) d4[i] = s4[i];
        s4 = reinterpret_cast<const float4*>(wv);  d4 = reinterpret_cast<float4*>(swv);
        for (int i = t; i < P*P/4; i += 256) d4[i] = s4[i];
        s4 = reinterpret_cast<const float4*>(wo);  d4 = reinterpret_cast<float4*>(swo);
        for (int i = t; i < P*P/4; i += 256) d4[i] = s4[i];
        s4 = reinterpret_cast<const float4*>(ctx_w); d4 = reinterpret_cast<float4*>(sctx);
        for (int i = t; i < P*C/4; i += 256) d4[i] = s4[i];
        s4 = reinterpret_cast<const float4*>(inp_w); d4 = reinterpret_cast<float4*>(sinp);
        for (int i = t; i < P*C/4; i += 256) d4[i] = s4[i];
    }
    if (t < C) gx[t] = g_gc[b*C + t];
    __syncthreads();

    if (t < P) {
        float a = ctx_b[t];
        for (int c = 0; c < C; c++) a += gx[c] * sctx[t*C + c];
        seq[0][t] = a;
    }
    for (int z = t; z < E*P; z += 256) seq[1 + z/P][z%P] = proto[z];
    __syncthreads();

    for (int z = t; z < SEQ*P; z += 256) {
        int s = z >> 6, p = z & 63;
        float aq = bq[p], ak = bk[p], av = bv[p];
        for (int q = 0; q < P; q++) {
            float sv = seq[s][q];
            aq += sv * swq[p*P + q];
            ak += sv * swk[p*P + q];
            av += sv * swv[p*P + q];
        }
        qs[s][p] = aq; ks[s][p] = ak; vs[s][p] = av;
    }
    __syncthreads();

    if (t < NH*SEQ) {
        int n = t / SEQ, i = t % SEQ;
        float sc[SEQ];
        float mx = -1e30f;
        for (int j = 0; j < SEQ; j++) {
            float a = 0.f;
            for (int d = 0; d < HD; d++) a += qs[i][n*HD + d] * ks[j][n*HD + d];
            a *= 0.25f;
            sc[j] = a; mx = fmaxf(mx, a);
        }
        float sm = 0.f;
        for (int j = 0; j < SEQ; j++) { sc[j] = expf(sc[j] - mx); sm += sc[j]; }
        float inv = 1.0f / sm;
        for (int d = 0; d < HD; d++) {
            float a = 0.f;
            for (int j = 0; j < SEQ; j++) a += sc[j] * vs[j][n*HD + d];
            ao[i][n*HD + d] = a * inv;
        }
    }
    __syncthreads();

    for (int z = t; z < SEQ*P; z += 256) {
        int s = z >> 6, p = z & 63;
        float a = bo[p];
        for (int q = 0; q < P; q++) a += ao[s][q] * swo[p*P + q];
        o2[s][p] = a + seq[s][p];
    }
    __syncthreads();

    if (t < SEQ) {
        float m = 0.f;
        for (int p = 0; p < P; p++) m += o2[t][p];
        m *= (1.0f / P);
        float v = 0.f;
        for (int p = 0; p < P; p++) { float d = o2[t][p] - m; v += d*d; }
        v *= (1.0f / P);
        mstat[t] = m; istat[t] = 1.0f / sqrtf(v + 1e-5f);
    }
    __syncthreads();

    for (int z = t; z < E*P; z += 256) {
        int s = z / P + 1, p = z % P;
        seq[s][p] = (o2[s][p] - mstat[s]) * istat[s] * ln_g[p] + ln_b[p];
    }
    __syncthreads();

    for (int z = t; z < E*C; z += 256) {
        int e = z / C, c = z % C;
        float a = 0.f;
        for (int p = 0; p < P; p++) a += seq[e+1][p] * sinp[p*C + c];
        g_Wr[(b*E + e)*C + c] = a;
    }
    if (t < E) {
        float a = 0.f;
        for (int p = 0; p < P; p++) a += seq[t+1][p] * inp_b[p];
        g_br[b*E + t] = a;
    }
}

// ---------------- kernel B: routing + per-expert compaction -------------
// 512 blocks x 256 threads; 64 pixels/block; 4 threads per pixel (c-slices).
__global__ void k_route(const float* __restrict__ x) {
    const int t = threadIdx.x;
    const int p = t & 63;
    const int j = t >> 6;
    const int pix0 = blockIdx.x * 64;
    const int b = pix0 / HW;
    const int pix = pix0 + p;

    __shared__ float wr[E*C];
    __shared__ float br[E];
    __shared__ float part[4][64*13];
    __shared__ float psum[E];
    __shared__ int   scnt[E], sbase[E];

    for (int i = t; i < E*C; i += 256) wr[i] = g_Wr[b*E*C + i];
    if (t < E) {
        br[t] = g_br[b*E + t];
        psum[t] = 0.f;
        scnt[t] = 0;
    }
    __syncthreads();

    {
        float pr[E];
        #pragma unroll
        for (int e = 0; e < E; e++) pr[e] = 0.f;
        const float* xp = x + (size_t)b*C*HW + (pix - b*HW);
        for (int ci = 0; ci < 32; ci++) {
            int c = j*32 + ci;
            float xv = xp[(size_t)c * HW];
            #pragma unroll
            for (int e = 0; e < E; e++) pr[e] += xv * wr[e*C + c];
        }
        #pragma unroll
        for (int e = 0; e < E; e++) part[j][p*13 + e] = pr[e];
    }
    __syncthreads();

    int loc[E];
    if (t < 64) {
        float pr[E];
        #pragma unroll
        for (int e = 0; e < E; e++)
            pr[e] = br[e] + part[0][t*13 + e] + part[1][t*13 + e]
                          + part[2][t*13 + e] + part[3][t*13 + e];

        float mx = -1e30f;
        #pragma unroll
        for (int e = 0; e < E; e++) { pr[e] *= 0.125f; mx = fmaxf(mx, pr[e]); }
        float sm = 0.f;
        #pragma unroll
        for (int e = 0; e < E; e++) { pr[e] = expf(pr[e] - mx); sm += pr[e]; }
        float invs = 1.0f / sm;
        #pragma unroll
        for (int e = 0; e < E; e++) pr[e] *= invs;

        int used = 0;
        float tsum = 0.f;
        #pragma unroll
        for (int k2 = 0; k2 < KSEL; k2++) {
            float bv = -1.f; int bi = 0;
            #pragma unroll
            for (int e = 0; e < E; e++)
                if (!((used >> e) & 1) && pr[e] > bv) { bv = pr[e]; bi = e; }
            used |= 1 << bi;
            tsum += bv;
        }
        float invt = 1.0f / tsum;

        #pragma unroll
        for (int e = 0; e < E; e++) {
            int selq = (used >> e) & 1;
            g_route[(size_t)e * NPIX + pix] = selq ? pr[e] * invt : 0.f;
            atomicAdd(&psum[e], pr[e]);
            loc[e] = selq ? atomicAdd(&scnt[e], 1) : -1;
        }
    }
    __syncthreads();
    if (t < E) {
        sbase[t] = atomicAdd(&g_cnt[t], scnt[t]);
        atomicAdd(&g_probsum[t], psum[t]);
        atomicAdd(&g_loadsum[t], (float)scnt[t]);
    }
    __syncthreads();
    if (t < 64) {
        #pragma unroll
        for (int e = 0; e < E; e++) {
            if (loc[e] >= 0) {
                int slot = sbase[e] + loc[e];
                g_pidx[e*NPIX + slot] = pix;
            }
        }
    }
}

// ---------------- kernel C: HMMA grouped-GEMM expert MLPs ----------------
// Double-buffered cp.async weight pipeline; fused atomic epilogue into out.
__global__ void __launch_bounds__(256, 1)
k_mlp(const float* __restrict__ x,
      const float* __restrict__ eb1,
      const float* __restrict__ eb2,
      float* __restrict__ out) {
    extern __shared__ __align__(16) __nv_bfloat16 sm[];
    __nv_bfloat16* Xh = sm;                  // [128][LDT]
    __nv_bfloat16* Wa = Xh + 128*LDT;        // W1 chunk
    __nv_bfloat16* Wb = Wa + 128*LDT;        // W2 chunk
    __nv_bfloat16* Hh = Wb + 128*LDT;
    __shared__ int   pid[128];
    __shared__ float wt[128];
    __shared__ float bias1[128], bias2[128];

    const int e     = blockIdx.y;
    const int cnt   = g_cnt[e];
    const int tile0 = blockIdx.x * 128;
    if (tile0 >= cnt) return;
    const int rem = min(128, cnt - tile0);
    const int tid = threadIdx.x;
    const int wid = tid >> 5, lane = tid & 31;

    const __nv_bfloat16* w1h = g_w1h + (size_t)e*HID*C;
    const __nv_bfloat16* w2h = g_w2h + (size_t)e*C*HID;

    const uint32_t uXh = smem_u32(Xh);
    const uint32_t uWa = smem_u32(Wa);
    const uint32_t uWb = smem_u32(Wb);
    const uint32_t uHh = smem_u32(Hh);

    // prologue: prefetch W1 chunk 0 into Wa
    #pragma unroll
    for (int k = 0; k < 8; k++) {
        int idx = tid + k*256;
        int row = idx >> 4, q = idx & 15;
        CP_ASYNC16(uWa + (uint32_t)(row*LDT + q*8)*2,
                   w1h + (size_t)row*C + q*8);
    }
    CP_COMMIT();

    if (tid < 128) {
        int p = g_pidx[e*NPIX + tile0 + min(tid, rem - 1)];
        pid[tid]   = p;
        wt[tid]    = g_route[(size_t)e*NPIX + p];
        bias2[tid] = eb2[(size_t)e*C + tid];
    }
    __syncthreads();

    // gather X -> bf16 [slot][c]  (overlaps with W1(0) prefetch)
    for (int idx = tid; idx < 128*128; idx += 256) {
        int slot = idx & 127, c = idx >> 7;
        int p = pid[slot];
        int b = p >> 12;
        float v = x[(size_t)b*(C-1)*HW + (size_t)c*HW + p];
        Xh[slot*LDT + c] = __float2bfloat16(v);
    }

    const int m0 = (wid >> 1) * 32;
    const int n0 = (wid & 1) * 64;
    const int lr = lane & 7, lq = lane >> 3;
    const int aoff = ((lr + (lq & 1)*8) * LDT + (lq >> 1)*8) * 2;
    const int boff = ((lr + (lq >> 1)*8) * LDT + (lq & 1)*8) * 2;
    const int er = lane >> 2;
    const int ec = (lane & 3) * 2;

    const uint32_t aXh = uXh + m0*LDT*2 + aoff;
    const uint32_t aHh = uHh + m0*LDT*2 + aoff;
    const uint32_t bW1 = uWa + n0*LDT*2 + boff;
    const uint32_t bW2 = uWb + n0*LDT*2 + boff;

    float yacc[2][8][4];
    #pragma unroll
    for (int mt = 0; mt < 2; mt++)
        #pragma unroll
        for (int nt = 0; nt < 8; nt++)
            #pragma unroll
            for (int q = 0; q < 4; q++) yacc[mt][nt][q] = 0.f;

    for (int rc = 0; rc < 4; rc++) {
        const int r0 = rc * 128;

        // issue W2(rc) -> Wb
        #pragma unroll
        for (int k = 0; k < 8; k++) {
            int idx = tid + k*256;
            int row = idx >> 4, q = idx & 15;
            CP_ASYNC16(uWb + (uint32_t)(row*LDT + q*8)*2,
                       w2h + (size_t)row*HID + r0 + q*8);
        }
        CP_COMMIT();
        if (tid < 128) bias1[tid] = eb1[(size_t)e*HID + r0 + tid];
        CP_WAIT1();                 // W1(rc) complete
        __syncthreads();

        // ---- GEMM1: H = X @ W1(rc)^T
        float h[2][8][4];
        #pragma unroll
        for (int mt = 0; mt < 2; mt++)
            #pragma unroll
            for (int nt = 0; nt < 8; nt++)
                #pragma unroll
                for (int q = 0; q < 4; q++) h[mt][nt][q] = 0.f;

        #pragma unroll 2
        for (int ks2 = 0; ks2 < 8; ks2++) {
            const uint32_t kb = ks2 * 32;
            uint32_t ah[2][4];
            ldsm4(aXh + kb,             ah[0]);
            ldsm4(aXh + kb + 16*LDT*2,  ah[1]);
            #pragma unroll
            for (int ntp = 0; ntp < 4; ntp++) {
                uint32_t bh[4];
                ldsm4(bW1 + ntp*16*LDT*2 + kb, bh);
                #pragma unroll
                for (int mt = 0; mt < 2; mt++) {
                    mma16816(h[mt][ntp*2],   ah[mt], bh);
                    mma16816(h[mt][ntp*2+1], ah[mt], bh + 2);
                }
            }
        }

        // ---- fast gelu + bias -> Hh
        #pragma unroll
        for (int mt = 0; mt < 2; mt++) {
            #pragma unroll
            for (int nt = 0; nt < 8; nt++) {
                int gm = m0 + mt*16 + er;
                int gn = n0 + nt*8 + ec;
                float b1a = bias1[gn], b1b = bias1[gn+1];
                float u0 = fast_gelu(h[mt][nt][0] + b1a);
                float u1 = fast_gelu(h[mt][nt][1] + b1b);
                float u2 = fast_gelu(h[mt][nt][2] + b1a);
                float u3 = fast_gelu(h[mt][nt][3] + b1b);
                *reinterpret_cast<uint32_t*>(Hh + gm*LDT + gn)     = pack_bf2(u0, u1);
                *reinterpret_cast<uint32_t*>(Hh + (gm+8)*LDT + gn) = pack_bf2(u2, u3);
            }
        }
        __syncthreads();            // Hh ready; Wa reads done

        // issue W1(rc+1) -> Wa
        if (rc < 3) {
            #pragma unroll
            for (int k = 0; k < 8; k++) {
                int idx = tid + k*256;
                int row = idx >> 4, q = idx & 15;
                CP_ASYNC16(uWa + (uint32_t)(row*LDT + q*8)*2,
                           w1h + (size_t)(r0 + 128 + row)*C + q*8);
            }
            CP_COMMIT();
            CP_WAIT1();             // W2(rc) complete
        } else {
            CP_WAIT0();
        }
        __syncthreads();

        // ---- GEMM2: Y += H @ W2(rc)^T
        #pragma unroll 2
        for (int ks2 = 0; ks2 < 8; ks2++) {
            const uint32_t kb = ks2 * 32;
            uint32_t ah[2][4];
            ldsm4(aHh + kb,            ah[0]);
            ldsm4(aHh + kb + 16*LDT*2, ah[1]);
            #pragma unroll
            for (int ntp = 0; ntp < 4; ntp++) {
                uint32_t bh[4];
                ldsm4(bW2 + ntp*16*LDT*2 + kb, bh);
                #pragma unroll
                for (int mt = 0; mt < 2; mt++) {
                    mma16816(yacc[mt][ntp*2],   ah[mt], bh);
                    mma16816(yacc[mt][ntp*2+1], ah[mt], bh + 2);
                }
            }
        }
        __syncthreads();            // Wb reads done before next fill
    }

    // ---- fused epilogue: out += wv * (y + b2), scattered atomics
    #pragma unroll
    for (int mt = 0; mt < 2; mt++) {
        #pragma unroll
        for (int nt = 0; nt < 8; nt++) {
            int slot = m0 + mt*16 + er;
            int cc   = n0 + nt*8 + ec;
            float b2a = bias2[cc], b2b = bias2[cc+1];
            if (slot < rem) {
                int p = pid[slot];
                int b = p >> 12;
                float w = wt[slot];
                float* dst = out + (size_t)b*(C-1)*HW + (size_t)cc*HW + p;
                atomicAdd(dst,      w * (yacc[mt][nt][0] + b2a));
                atomicAdd(dst + HW, w * (yacc[mt][nt][1] + b2b));
            }
            if (slot + 8 < rem) {
                int p = pid[slot + 8];
                int b = p >> 12;
                float w = wt[slot + 8];
                float* dst = out + (size_t)b*(C-1)*HW + (size_t)cc*HW + p;
                atomicAdd(dst,      w * (yacc[mt][nt][2] + b2a));
                atomicAdd(dst + HW, w * (yacc[mt][nt][3] + b2b));
            }
        }
    }
}

// ---------------- kernel D: aux scalar -----------------------------------
__global__ void k_aux(const float* __restrict__ proto, float* __restrict__ out, int out_size) {
    __shared__ float pn[E][P];
    __shared__ float red[128];
    int t = threadIdx.x;
    if (t < E) {
        float s = 0.f;
        for (int p = 0; p < P; p++) { float v = proto[t*P + p]; s += v*v; }
        float inv = 1.0f / sqrtf(s);
        for (int p = 0; p < P; p++) pn[t][p] = proto[t*P + p] * inv;
    }
    __syncthreads();
    float s = 0.f;
    for (int idx = t; idx < E*E; idx += 128) {
        int i = idx / E, j = idx % E;
        float d = 0.f;
        for (int p = 0; p < P; p++) d += pn[i][p] * pn[j][p];
        d -= (i == j) ? 1.0f : 0.0f;
        s += d*d;
    }
    red[t] = s;
    __syncthreads();
    for (int st = 64; st; st >>= 1) { if (t < st) red[t] += red[t + st]; __syncthreads(); }
    if (t == 0) {
        float ortho = sqrtf(red[0]);
        float aux = 0.f;
        for (int e = 0; e < E; e++)
            aux += (g_probsum[e] * (1.0f/NPIX)) * (g_loadsum[e] * (1.0f/NPIX));
        aux *= (float)E;
        if (out_size > BB*C*HW) out[BB*C*HW] = aux + 0.5f * ortho;
    }
}

// ---------------- launcher ------------------------------------------------
extern "C" void kernel_launch(void* const* d_in, const int* in_sizes, int n_in,
                              void* d_out, int out_size) {
    const float* x      = (const float*)d_in[0];
    const float* proto  = (const float*)d_in[1];
    const float* ctx_w  = (const float*)d_in[2];
    const float* ctx_b  = (const float*)d_in[3];
    const float* inp_w  = (const float*)d_in[4];
    const float* inp_b  = (const float*)d_in[5];
    const float* wq     = (const float*)d_in[6];
    const float* bq     = (const float*)d_in[7];
    const float* wk     = (const float*)d_in[8];
    const float* bk     = (const float*)d_in[9];
    const float* wv     = (const float*)d_in[10];
    const float* bv     = (const float*)d_in[11];
    const float* wo     = (const float*)d_in[12];
    const float* bo     = (const float*)d_in[13];
    const float* ln_g   = (const float*)d_in[14];
    const float* ln_b   = (const float*)d_in[15];
    const float* ew1    = (const float*)d_in[16];
    const float* eb1    = (const float*)d_in[17];
    const float* ew2    = (const float*)d_in[18];
    const float* eb2    = (const float*)d_in[19];
    float* out = (float*)d_out;

    const int smem_mlp  = 4 * 128 * LDT * (int)sizeof(__nv_bfloat16);  // 139264 B
    const int smem_attn = (4*P*P + 2*P*C) * (int)sizeof(float);        // 131072 B
    cudaFuncSetAttribute(k_mlp,  cudaFuncAttributeMaxDynamicSharedMemorySize, smem_mlp);
    cudaFuncSetAttribute(k_attn, cudaFuncAttributeMaxDynamicSharedMemorySize, smem_attn);

    k_cvt<<<(E*HID*C + 255)/256, 256>>>(ew1, ew2);
    k_gc<<<BB*C, 128>>>(x, out);
    k_attn<<<BB, 256, smem_attn>>>(proto, ctx_w, ctx_b, inp_w, inp_b,
                                   wq, bq, wk, bk, wv, bv, wo, bo, ln_g, ln_b);
    k_route<<<NPIX/64, 256>>>(x);
    k_mlp<<<dim3(NPIX/128, E), 256, smem_mlp>>>(x, eb1, eb2, out);
    k_aux<<<1, 128>>>(proto, out, out_size);
}

// round 17
// speedup vs baseline: 1.5137x; 1.0335x over previous
#include <cuda_runtime.h>
#include <cuda_bf16.h>
#include <math.h>
#include <stdint.h>

#define E    11
#define KSEL 6
#define P    64
#define NH   4
#define HD   16
#define SEQ  12
#define BB   8
#define C    128
#define HH   64
#define WW   64
#define HW   (HH*WW)        /* 4096  */
#define NPIX (BB*HW)        /* 32768 */
#define HID  512
#define LDT  136            /* smem tile row stride in bf16 (272B = 17*16B, conflict-free) */

// ---------------- device scratch (no allocation allowed) ----------------
__device__ float g_gc[BB*C];
__device__ float g_Wr[BB*E*C];
__device__ float g_br[BB*E];
__device__ float g_route[E*NPIX];
__device__ float g_probsum[E];
__device__ float g_loadsum[E];
__device__ int   g_cnt[E];
__device__ int   g_pidx[E*NPIX];   // [e][slot] -> pixel
__device__ __align__(16) __nv_bfloat16 g_w1h[E*HID*C];  // [e][r][c]
__device__ __align__(16) __nv_bfloat16 g_w2h[E*C*HID];  // [e][c][j]

// ---------------- mma/ldmatrix helpers (sm_80-era, no 'a' gating) --------
__device__ __forceinline__ uint32_t smem_u32(const void* p) {
    uint32_t a;
    asm("{ .reg .u64 t; cvta.to.shared.u64 t, %1; cvt.u32.u64 %0, t; }"
        : "=r"(a) : "l"(p));
    return a;
}
__device__ __forceinline__ void ldsm4(uint32_t a, uint32_t* r) {
    asm volatile("ldmatrix.sync.aligned.m8n8.x4.shared.b16 {%0,%1,%2,%3}, [%4];"
        : "=r"(r[0]), "=r"(r[1]), "=r"(r[2]), "=r"(r[3]) : "r"(a));
}
__device__ __forceinline__ void mma16816(float* c, const uint32_t* a, const uint32_t* b) {
    asm volatile("mma.sync.aligned.m16n8k16.row.col.f32.bf16.bf16.f32 "
        "{%0,%1,%2,%3}, {%4,%5,%6,%7}, {%8,%9}, {%0,%1,%2,%3};"
        : "+f"(c[0]), "+f"(c[1]), "+f"(c[2]), "+f"(c[3])
        : "r"(a[0]), "r"(a[1]), "r"(a[2]), "r"(a[3]), "r"(b[0]), "r"(b[1]));
}
__device__ __forceinline__ uint32_t pack_bf2(float x, float y) {
    __nv_bfloat162 v = __floats2bfloat162_rn(x, y);
    return *reinterpret_cast<uint32_t*>(&v);
}
// fast gelu: u / (1 + exp(-(1.5957691*u + 0.0713548*u^3)))
__device__ __forceinline__ float fast_gelu(float u) {
    float z = u * fmaf(u*u, 0.0713548162726f, 1.5957691216057f);
    return __fdividef(u, 1.0f + __expf(-z));
}
#define CP_ASYNC16(dst, src) \
    asm volatile("cp.async.cg.shared.global [%0], [%1], 16;" :: "r"(dst), "l"(src))
#define CP_COMMIT() asm volatile("cp.async.commit_group;" ::: "memory")
#define CP_WAIT1()  asm volatile("cp.async.wait_group 1;" ::: "memory")
#define CP_WAIT0()  asm volatile("cp.async.wait_group 0;" ::: "memory")

// ---------------- prep: convert weights to bf16 ---------------------------
__global__ void k_cvt(const float* __restrict__ ew1, const float* __restrict__ ew2) {
    int i = blockIdx.x * 256 + threadIdx.x;
    if (i < E*HID*C) {
        g_w1h[i] = __float2bfloat16(ew1[i]);
        g_w2h[i] = __float2bfloat16(ew2[i]);
    }
}

// ---------------- kernel 0: gc means + out=x + zero counters ------------
__global__ void k_gc(const float* __restrict__ x, float* __restrict__ out) {
    int bc = blockIdx.x;
    const float4* src = reinterpret_cast<const float4*>(x + (size_t)bc * HW);
    float4* dst = reinterpret_cast<float4*>(out + (size_t)bc * HW);
    float s = 0.f;
    for (int i = threadIdx.x; i < HW/4; i += 128) {
        float4 v = src[i];
        dst[i] = v;                                // residual init: out = x
        s += v.x + v.y + v.z + v.w;
    }
    __shared__ float red[4];
    for (int o = 16; o; o >>= 1) s += __shfl_down_sync(0xffffffffu, s, o);
    if ((threadIdx.x & 31) == 0) red[threadIdx.x >> 5] = s;
    __syncthreads();
    if (threadIdx.x == 0) {
        float t = red[0] + red[1] + red[2] + red[3];
        g_gc[bc] = t * (1.0f / HW);
    }
    if (bc == 0 && threadIdx.x < E) {
        g_probsum[threadIdx.x] = 0.f;
        g_loadsum[threadIdx.x] = 0.f;
        g_cnt[threadIdx.x] = 0;
    }
}

// ---------------- kernel A: attention path + router weight folding ------
__global__ void k_attn(const float* __restrict__ proto,
                       const float* __restrict__ ctx_w, const float* __restrict__ ctx_b,
                       const float* __restrict__ inp_w, const float* __restrict__ inp_b,
                       const float* __restrict__ wq, const float* __restrict__ bq,
                       const float* __restrict__ wk, const float* __restrict__ bk,
                       const float* __restrict__ wv, const float* __restrict__ bv,
                       const float* __restrict__ wo, const float* __restrict__ bo,
                       const float* __restrict__ ln_g, const float* __restrict__ ln_b) {
    extern __shared__ float wsm[];
    float* swq  = wsm;               // P*P = 4096
    float* swk  = swq + P*P;
    float* swv  = swk + P*P;
    float* swo  = swv + P*P;
    float* sctx = swo + P*P;         // P*C = 8192
    float* sinp = sctx + P*C;        // P*C = 8192

    int b = blockIdx.x;
    int t = threadIdx.x;                       // 256 threads
    __shared__ float seq[SEQ][P], qs[SEQ][P], ks[SEQ][P], vs[SEQ][P], ao[SEQ][P], o2[SEQ][P];
    __shared__ float gx[C];
    __shared__ float mstat[SEQ], istat[SEQ];

    {
        const float4* s4;
        float4* d4;
        s4 = reinterpret_cast<const float4*>(wq);  d4 = reinterpret_cast<float4*>(swq);
        for (int i = t; i < P*P/4; i += 256) d4[i] = s4[i];
        s4 = reinterpret_cast<const float4*>(wk);  d4 = reinterpret_cast<float4*>(swk);
        for (int i = t; i < P*P/4; i += 256) d4[i] = s4[i];
        s4 = reinterpret_cast<const float4*>(wv);  d4 = reinterpret_cast<float4*>(swv);
        for (int i = t; i < P*P/4; i += 256) d4[i] = s4[i];
        s4 = reinterpret_cast<const float4*>(wo);  d4 = reinterpret_cast<float4*>(swo);
        for (int i = t; i < P*P/4; i += 256) d4[i] = s4[i];
        s4 = reinterpret_cast<const float4*>(ctx_w); d4 = reinterpret_cast<float4*>(sctx);
        for (int i = t; i < P*C/4; i += 256) d4[i] = s4[i];
        s4 = reinterpret_cast<const float4*>(inp_w); d4 = reinterpret_cast<float4*>(sinp);
        for (int i = t; i < P*C/4; i += 256) d4[i] = s4[i];
    }
    if (t < C) gx[t] = g_gc[b*C + t];
    __syncthreads();

    if (t < P) {
        float a = ctx_b[t];
        for (int c = 0; c < C; c++) a += gx[c] * sctx[t*C + c];
        seq[0][t] = a;
    }
    for (int z = t; z < E*P; z += 256) seq[1 + z/P][z%P] = proto[z];
    __syncthreads();

    for (int z = t; z < SEQ*P; z += 256) {
        int s = z >> 6, p = z & 63;
        float aq = bq[p], ak = bk[p], av = bv[p];
        for (int q = 0; q < P; q++) {
            float sv = seq[s][q];
            aq += sv * swq[p*P + q];
            ak += sv * swk[p*P + q];
            av += sv * swv[p*P + q];
        }
        qs[s][p] = aq; ks[s][p] = ak; vs[s][p] = av;
    }
    __syncthreads();

    if (t < NH*SEQ) {
        int n = t / SEQ, i = t % SEQ;
        float sc[SEQ];
        float mx = -1e30f;
        for (int j = 0; j < SEQ; j++) {
            float a = 0.f;
            for (int d = 0; d < HD; d++) a += qs[i][n*HD + d] * ks[j][n*HD + d];
            a *= 0.25f;
            sc[j] = a; mx = fmaxf(mx, a);
        }
        float sm = 0.f;
        for (int j = 0; j < SEQ; j++) { sc[j] = expf(sc[j] - mx); sm += sc[j]; }
        float inv = 1.0f / sm;
        for (int d = 0; d < HD; d++) {
            float a = 0.f;
            for (int j = 0; j < SEQ; j++) a += sc[j] * vs[j][n*HD + d];
            ao[i][n*HD + d] = a * inv;
        }
    }
    __syncthreads();

    for (int z = t; z < SEQ*P; z += 256) {
        int s = z >> 6, p = z & 63;
        float a = bo[p];
        for (int q = 0; q < P; q++) a += ao[s][q] * swo[p*P + q];
        o2[s][p] = a + seq[s][p];
    }
    __syncthreads();

    if (t < SEQ) {
        float m = 0.f;
        for (int p = 0; p < P; p++) m += o2[t][p];
        m *= (1.0f / P);
        float v = 0.f;
        for (int p = 0; p < P; p++) { float d = o2[t][p] - m; v += d*d; }
        v *= (1.0f / P);
        mstat[t] = m; istat[t] = 1.0f / sqrtf(v + 1e-5f);
    }
    __syncthreads();

    for (int z = t; z < E*P; z += 256) {
        int s = z / P + 1, p = z % P;
        seq[s][p] = (o2[s][p] - mstat[s]) * istat[s] * ln_g[p] + ln_b[p];
    }
    __syncthreads();

    for (int z = t; z < E*C; z += 256) {
        int e = z / C, c = z % C;
        float a = 0.f;
        for (int p = 0; p < P; p++) a += seq[e+1][p] * sinp[p*C + c];
        g_Wr[(b*E + e)*C + c] = a;
    }
    if (t < E) {
        float a = 0.f;
        for (int p = 0; p < P; p++) a += seq[t+1][p] * inp_b[p];
        g_br[b*E + t] = a;
    }
}

// ---------------- kernel B: routing + per-expert compaction -------------
// 1024 blocks x 256 threads; 32 pixels/block; 8 threads per pixel (c-slices).
__global__ void k_route(const float* __restrict__ x) {
    const int t = threadIdx.x;
    const int p = t & 31;                  // pixel within block
    const int j = t >> 5;                  // c-slice 0..7
    const int pix0 = blockIdx.x * 32;
    const int b = pix0 / HW;               // 32 | 4096 -> whole block same batch
    const int pix = pix0 + p;

    __shared__ float wr[E*C];
    __shared__ float br[E];
    __shared__ float part[8][32*13];       // stride 13: conflict-free
    __shared__ float psum[E];
    __shared__ int   scnt[E], sbase[E];

    for (int i = t; i < E*C; i += 256) wr[i] = g_Wr[b*E*C + i];
    if (t < E) {
        br[t] = g_br[b*E + t];
        psum[t] = 0.f;
        scnt[t] = 0;
    }
    __syncthreads();

    // partial logits over c-slice j (16 channels)
    {
        float pr[E];
        #pragma unroll
        for (int e = 0; e < E; e++) pr[e] = 0.f;
        const float* xp = x + (size_t)b*C*HW + (pix - b*HW);
        for (int ci = 0; ci < 16; ci++) {
            int c = j*16 + ci;
            float xv = xp[(size_t)c * HW];
            #pragma unroll
            for (int e = 0; e < E; e++) pr[e] += xv * wr[e*C + c];
        }
        #pragma unroll
        for (int e = 0; e < E; e++) part[j][p*13 + e] = pr[e];
    }
    __syncthreads();

    int loc[E];
    if (t < 32) {
        float pr[E];
        #pragma unroll
        for (int e = 0; e < E; e++) {
            float a = br[e];
            #pragma unroll
            for (int jj = 0; jj < 8; jj++) a += part[jj][t*13 + e];
            pr[e] = a;
        }

        float mx = -1e30f;
        #pragma unroll
        for (int e = 0; e < E; e++) { pr[e] *= 0.125f; mx = fmaxf(mx, pr[e]); }
        float sm = 0.f;
        #pragma unroll
        for (int e = 0; e < E; e++) { pr[e] = expf(pr[e] - mx); sm += pr[e]; }
        float invs = 1.0f / sm;
        #pragma unroll
        for (int e = 0; e < E; e++) pr[e] *= invs;

        int used = 0;
        float tsum = 0.f;
        #pragma unroll
        for (int k2 = 0; k2 < KSEL; k2++) {
            float bv = -1.f; int bi = 0;
            #pragma unroll
            for (int e = 0; e < E; e++)
                if (!((used >> e) & 1) && pr[e] > bv) { bv = pr[e]; bi = e; }
            used |= 1 << bi;
            tsum += bv;
        }
        float invt = 1.0f / tsum;

        #pragma unroll
        for (int e = 0; e < E; e++) {
            int selq = (used >> e) & 1;
            g_route[(size_t)e * NPIX + pix] = selq ? pr[e] * invt : 0.f;
            atomicAdd(&psum[e], pr[e]);
            loc[e] = selq ? atomicAdd(&scnt[e], 1) : -1;
        }
    }
    __syncthreads();
    if (t < E) {
        sbase[t] = atomicAdd(&g_cnt[t], scnt[t]);
        atomicAdd(&g_probsum[t], psum[t]);
        atomicAdd(&g_loadsum[t], (float)scnt[t]);
    }
    __syncthreads();
    if (t < 32) {
        #pragma unroll
        for (int e = 0; e < E; e++) {
            if (loc[e] >= 0) {
                int slot = sbase[e] + loc[e];
                g_pidx[e*NPIX + slot] = pix;
            }
        }
    }
}

// ---------------- kernel C: HMMA grouped-GEMM expert MLPs ----------------
// Double-buffered cp.async weight pipeline; fused atomic epilogue into out.
__global__ void __launch_bounds__(256, 1)
k_mlp(const float* __restrict__ x,
      const float* __restrict__ eb1,
      const float* __restrict__ eb2,
      float* __restrict__ out) {
    extern __shared__ __align__(16) __nv_bfloat16 sm[];
    __nv_bfloat16* Xh = sm;                  // [128][LDT]
    __nv_bfloat16* Wa = Xh + 128*LDT;        // W1 chunk
    __nv_bfloat16* Wb = Wa + 128*LDT;        // W2 chunk
    __nv_bfloat16* Hh = Wb + 128*LDT;
    __shared__ int   pid[128];
    __shared__ float wt[128];
    __shared__ float bias1[128], bias2[128];

    const int e     = blockIdx.y;
    const int cnt   = g_cnt[e];
    const int tile0 = blockIdx.x * 128;
    if (tile0 >= cnt) return;
    const int rem = min(128, cnt - tile0);
    const int tid = threadIdx.x;
    const int wid = tid >> 5, lane = tid & 31;

    const __nv_bfloat16* w1h = g_w1h + (size_t)e*HID*C;
    const __nv_bfloat16* w2h = g_w2h + (size_t)e*C*HID;

    const uint32_t uXh = smem_u32(Xh);
    const uint32_t uWa = smem_u32(Wa);
    const uint32_t uWb = smem_u32(Wb);
    const uint32_t uHh = smem_u32(Hh);

    // prologue: prefetch W1 chunk 0 into Wa
    #pragma unroll
    for (int k = 0; k < 8; k++) {
        int idx = tid + k*256;
        int row = idx >> 4, q = idx & 15;
        CP_ASYNC16(uWa + (uint32_t)(row*LDT + q*8)*2,
                   w1h + (size_t)row*C + q*8);
    }
    CP_COMMIT();

    if (tid < 128) {
        int p = g_pidx[e*NPIX + tile0 + min(tid, rem - 1)];
        pid[tid]   = p;
        wt[tid]    = g_route[(size_t)e*NPIX + p];
        bias2[tid] = eb2[(size_t)e*C + tid];
    }
    __syncthreads();

    // gather X -> bf16 [slot][c]  (overlaps with W1(0) prefetch)
    for (int idx = tid; idx < 128*128; idx += 256) {
        int slot = idx & 127, c = idx >> 7;
        int p = pid[slot];
        int b = p >> 12;
        float v = x[(size_t)b*(C-1)*HW + (size_t)c*HW + p];
        Xh[slot*LDT + c] = __float2bfloat16(v);
    }

    const int m0 = (wid >> 1) * 32;
    const int n0 = (wid & 1) * 64;
    const int lr = lane & 7, lq = lane >> 3;
    const int aoff = ((lr + (lq & 1)*8) * LDT + (lq >> 1)*8) * 2;
    const int boff = ((lr + (lq >> 1)*8) * LDT + (lq & 1)*8) * 2;
    const int er = lane >> 2;
    const int ec = (lane & 3) * 2;

    const uint32_t aXh = uXh + m0*LDT*2 + aoff;
    const uint32_t aHh = uHh + m0*LDT*2 + aoff;
    const uint32_t bW1 = uWa + n0*LDT*2 + boff;
    const uint32_t bW2 = uWb + n0*LDT*2 + boff;

    float yacc[2][8][4];
    #pragma unroll
    for (int mt = 0; mt < 2; mt++)
        #pragma unroll
        for (int nt = 0; nt < 8; nt++)
            #pragma unroll
            for (int q = 0; q < 4; q++) yacc[mt][nt][q] = 0.f;

    for (int rc = 0; rc < 4; rc++) {
        const int r0 = rc * 128;

        // issue W2(rc) -> Wb
        #pragma unroll
        for (int k = 0; k < 8; k++) {
            int idx = tid + k*256;
            int row = idx >> 4, q = idx & 15;
            CP_ASYNC16(uWb + (uint32_t)(row*LDT + q*8)*2,
                       w2h + (size_t)row*HID + r0 + q*8);
        }
        CP_COMMIT();
        if (tid < 128) bias1[tid] = eb1[(size_t)e*HID + r0 + tid];
        CP_WAIT1();                 // W1(rc) complete
        __syncthreads();

        // ---- GEMM1: H = X @ W1(rc)^T
        float h[2][8][4];
        #pragma unroll
        for (int mt = 0; mt < 2; mt++)
            #pragma unroll
            for (int nt = 0; nt < 8; nt++)
                #pragma unroll
                for (int q = 0; q < 4; q++) h[mt][nt][q] = 0.f;

        #pragma unroll 2
        for (int ks2 = 0; ks2 < 8; ks2++) {
            const uint32_t kb = ks2 * 32;
            uint32_t ah[2][4];
            ldsm4(aXh + kb,             ah[0]);
            ldsm4(aXh + kb + 16*LDT*2,  ah[1]);
            #pragma unroll
            for (int ntp = 0; ntp < 4; ntp++) {
                uint32_t bh[4];
                ldsm4(bW1 + ntp*16*LDT*2 + kb, bh);
                #pragma unroll
                for (int mt = 0; mt < 2; mt++) {
                    mma16816(h[mt][ntp*2],   ah[mt], bh);
                    mma16816(h[mt][ntp*2+1], ah[mt], bh + 2);
                }
            }
        }

        // ---- fast gelu + bias -> Hh
        #pragma unroll
        for (int mt = 0; mt < 2; mt++) {
            #pragma unroll
            for (int nt = 0; nt < 8; nt++) {
                int gm = m0 + mt*16 + er;
                int gn = n0 + nt*8 + ec;
                float b1a = bias1[gn], b1b = bias1[gn+1];
                float u0 = fast_gelu(h[mt][nt][0] + b1a);
                float u1 = fast_gelu(h[mt][nt][1] + b1b);
                float u2 = fast_gelu(h[mt][nt][2] + b1a);
                float u3 = fast_gelu(h[mt][nt][3] + b1b);
                *reinterpret_cast<uint32_t*>(Hh + gm*LDT + gn)     = pack_bf2(u0, u1);
                *reinterpret_cast<uint32_t*>(Hh + (gm+8)*LDT + gn) = pack_bf2(u2, u3);
            }
        }
        __syncthreads();            // Hh ready; Wa reads done

        // issue W1(rc+1) -> Wa
        if (rc < 3) {
            #pragma unroll
            for (int k = 0; k < 8; k++) {
                int idx = tid + k*256;
                int row = idx >> 4, q = idx & 15;
                CP_ASYNC16(uWa + (uint32_t)(row*LDT + q*8)*2,
                           w1h + (size_t)(r0 + 128 + row)*C + q*8);
            }
            CP_COMMIT();
            CP_WAIT1();             // W2(rc) complete
        } else {
            CP_WAIT0();
        }
        __syncthreads();

        // ---- GEMM2: Y += H @ W2(rc)^T
        #pragma unroll 2
        for (int ks2 = 0; ks2 < 8; ks2++) {
            const uint32_t kb = ks2 * 32;
            uint32_t ah[2][4];
            ldsm4(aHh + kb,            ah[0]);
            ldsm4(aHh + kb + 16*LDT*2, ah[1]);
            #pragma unroll
            for (int ntp = 0; ntp < 4; ntp++) {
                uint32_t bh[4];
                ldsm4(bW2 + ntp*16*LDT*2 + kb, bh);
                #pragma unroll
                for (int mt = 0; mt < 2; mt++) {
                    mma16816(yacc[mt][ntp*2],   ah[mt], bh);
                    mma16816(yacc[mt][ntp*2+1], ah[mt], bh + 2);
                }
            }
        }
        __syncthreads();            // Wb reads done before next fill
    }

    // ---- fused epilogue: out += wv * (y + b2), scattered atomics
    #pragma unroll
    for (int mt = 0; mt < 2; mt++) {
        #pragma unroll
        for (int nt = 0; nt < 8; nt++) {
            int slot = m0 + mt*16 + er;
            int cc   = n0 + nt*8 + ec;
            float b2a = bias2[cc], b2b = bias2[cc+1];
            if (slot < rem) {
                int p = pid[slot];
                int b = p >> 12;
                float w = wt[slot];
                float* dst = out + (size_t)b*(C-1)*HW + (size_t)cc*HW + p;
                atomicAdd(dst,      w * (yacc[mt][nt][0] + b2a));
                atomicAdd(dst + HW, w * (yacc[mt][nt][1] + b2b));
            }
            if (slot + 8 < rem) {
                int p = pid[slot + 8];
                int b = p >> 12;
                float w = wt[slot + 8];
                float* dst = out + (size_t)b*(C-1)*HW + (size_t)cc*HW + p;
                atomicAdd(dst,      w * (yacc[mt][nt][2] + b2a));
                atomicAdd(dst + HW, w * (yacc[mt][nt][3] + b2b));
            }
        }
    }
}

// ---------------- kernel D: aux scalar -----------------------------------
__global__ void k_aux(const float* __restrict__ proto, float* __restrict__ out, int out_size) {
    __shared__ float pn[E][P];
    __shared__ float red[128];
    int t = threadIdx.x;
    if (t < E) {
        float s = 0.f;
        for (int p = 0; p < P; p++) { float v = proto[t*P + p]; s += v*v; }
        float inv = 1.0f / sqrtf(s);
        for (int p = 0; p < P; p++) pn[t][p] = proto[t*P + p] * inv;
    }
    __syncthreads();
    float s = 0.f;
    for (int idx = t; idx < E*E; idx += 128) {
        int i = idx / E, j = idx % E;
        float d = 0.f;
        for (int p = 0; p < P; p++) d += pn[i][p] * pn[j][p];
        d -= (i == j) ? 1.0f : 0.0f;
        s += d*d;
    }
    red[t] = s;
    __syncthreads();
    for (int st = 64; st; st >>= 1) { if (t < st) red[t] += red[t + st]; __syncthreads(); }
    if (t == 0) {
        float ortho = sqrtf(red[0]);
        float aux = 0.f;
        for (int e = 0; e < E; e++)
            aux += (g_probsum[e] * (1.0f/NPIX)) * (g_loadsum[e] * (1.0f/NPIX));
        aux *= (float)E;
        if (out_size > BB*C*HW) out[BB*C*HW] = aux + 0.5f * ortho;
    }
}

// ---------------- launcher ------------------------------------------------
extern "C" void kernel_launch(void* const* d_in, const int* in_sizes, int n_in,
                              void* d_out, int out_size) {
    const float* x      = (const float*)d_in[0];
    const float* proto  = (const float*)d_in[1];
    const float* ctx_w  = (const float*)d_in[2];
    const float* ctx_b  = (const float*)d_in[3];
    const float* inp_w  = (const float*)d_in[4];
    const float* inp_b  = (const float*)d_in[5];
    const float* wq     = (const float*)d_in[6];
    const float* bq     = (const float*)d_in[7];
    const float* wk     = (const float*)d_in[8];
    const float* bk     = (const float*)d_in[9];
    const float* wv     = (const float*)d_in[10];
    const float* bv     = (const float*)d_in[11];
    const float* wo     = (const float*)d_in[12];
    const float* bo     = (const float*)d_in[13];
    const float* ln_g   = (const float*)d_in[14];
    const float* ln_b   = (const float*)d_in[15];
    const float* ew1    = (const float*)d_in[16];
    const float* eb1    = (const float*)d_in[17];
    const float* ew2    = (const float*)d_in[18];
    const float* eb2    = (const float*)d_in[19];
    float* out = (float*)d_out;

    const int smem_mlp  = 4 * 128 * LDT * (int)sizeof(__nv_bfloat16);  // 139264 B
    const int smem_attn = (4*P*P + 2*P*C) * (int)sizeof(float);        // 131072 B
    cudaFuncSetAttribute(k_mlp,  cudaFuncAttributeMaxDynamicSharedMemorySize, smem_mlp);
    cudaFuncSetAttribute(k_attn, cudaFuncAttributeMaxDynamicSharedMemorySize, smem_attn);

    k_cvt<<<(E*HID*C + 255)/256, 256>>>(ew1, ew2);
    k_gc<<<BB*C, 128>>>(x, out);
    k_attn<<<BB, 256, smem_attn>>>(proto, ctx_w, ctx_b, inp_w, inp_b,
                                   wq, bq, wk, bk, wv, bv, wo, bo, ln_g, ln_b);
    k_route<<<NPIX/32, 256>>>(x);
    k_mlp<<<dim3(NPIX/128, E), 256, smem_mlp>>>(x, eb1, eb2, out);
    k_aux<<<1, 128>>>(proto, out, out_size);
}